// round 2
// baseline (speedup 1.0000x reference)
#include <cuda_runtime.h>
#include <cuda_bf16.h>

// Problem constants
#define BATCH 256
#define VPM   5850
#define NV    (BATCH*VPM)      // 1,497,600 vertices
#define NE    (3*NV)           // 4,492,800 edges
#define KDIM  (VPM*10)         // 58,500
#define NOUT  64
#define NEG_SLOPE 0.01f

// ---------------- scratch (device globals: allocation-free) ----------------
__device__ int   g_deg[NV];            //  6.0 MB
__device__ float g_agg1[NV*4];         // 24.0 MB (3 used, padded to 4)
__device__ float g_x1[NV*8];           // 48.0 MB (5 used, padded to 8)
__device__ float g_agg2[NV*8];         // 48.0 MB (5 used, padded to 8)
__device__ float g_h[NV*10];           // 60.0 MB  == (B, 58500) row-major
__device__ float g_logits[BATCH*NOUT]; // 64 KB

__device__ __forceinline__ float leaky(float t) {
    return t >= 0.f ? t : NEG_SLOPE * t;
}

// ---------------- K1: edge pass 1 — degree + raw-vert aggregation ----------
__global__ void k1_edge_agg1(const int* __restrict__ edges,
                             const float* __restrict__ verts) {
    int e = blockIdx.x * blockDim.x + threadIdx.x;
    if (e >= NE) return;
    int2 ep = __ldg(((const int2*)edges) + e);
    int i = ep.x, j = ep.y;
    atomicAdd(&g_deg[i], 1);
    atomicAdd(&g_deg[j], 1);
    float vj0 = __ldg(verts + 3*j+0), vj1 = __ldg(verts + 3*j+1), vj2 = __ldg(verts + 3*j+2);
    float vi0 = __ldg(verts + 3*i+0), vi1 = __ldg(verts + 3*i+1), vi2 = __ldg(verts + 3*i+2);
    atomicAdd(&g_agg1[4*i+0], vj0);
    atomicAdd(&g_agg1[4*i+1], vj1);
    atomicAdd(&g_agg1[4*i+2], vj2);
    atomicAdd(&g_agg1[4*j+0], vi0);
    atomicAdd(&g_agg1[4*j+1], vi1);
    atomicAdd(&g_agg1[4*j+2], vi2);
}

// ---------------- K2: vertex pass 1 — x1 = leaky(gc1) ----------------------
__global__ void k2_vert1(const float* __restrict__ verts,
                         const float* __restrict__ w0a, const float* __restrict__ b0a,
                         const float* __restrict__ w1a, const float* __restrict__ b1a) {
    int v = blockIdx.x * blockDim.x + threadIdx.x;
    if (v >= NV) return;
    float p[3], a[3];
    p[0] = verts[3*v+0]; p[1] = verts[3*v+1]; p[2] = verts[3*v+2];
    float4 a4 = *(const float4*)&g_agg1[4*v];
    a[0] = a4.x; a[1] = a4.y; a[2] = a4.z;
    float dg = (float)g_deg[v];
    float x[5];
#pragma unroll
    for (int k = 0; k < 5; k++) {
        float t = __ldg(b0a + k) + dg * __ldg(b1a + k);
#pragma unroll
        for (int c = 0; c < 3; c++)
            t += __ldg(w0a + k*3 + c) * p[c] + __ldg(w1a + k*3 + c) * a[c];
        x[k] = leaky(t);
    }
    // padded coalesced 32B store
    float4 o0 = make_float4(x[0], x[1], x[2], x[3]);
    float4 o1 = make_float4(x[4], 0.f, 0.f, 0.f);
    *(float4*)&g_x1[8*v]     = o0;
    *(float4*)&g_x1[8*v + 4] = o1;
}

// ---------------- K3: edge pass 2 — aggregate x1 ---------------------------
__global__ void k3_edge_agg2(const int* __restrict__ edges) {
    int e = blockIdx.x * blockDim.x + threadIdx.x;
    if (e >= NE) return;
    int2 ep = __ldg(((const int2*)edges) + e);
    int i = ep.x, j = ep.y;
    float4 xj4 = __ldg((const float4*)&g_x1[8*j]);
    float  xj4e = __ldg(&g_x1[8*j + 4]);
    float4 xi4 = __ldg((const float4*)&g_x1[8*i]);
    float  xi4e = __ldg(&g_x1[8*i + 4]);
    atomicAdd(&g_agg2[8*i+0], xj4.x);
    atomicAdd(&g_agg2[8*i+1], xj4.y);
    atomicAdd(&g_agg2[8*i+2], xj4.z);
    atomicAdd(&g_agg2[8*i+3], xj4.w);
    atomicAdd(&g_agg2[8*i+4], xj4e);
    atomicAdd(&g_agg2[8*j+0], xi4.x);
    atomicAdd(&g_agg2[8*j+1], xi4.y);
    atomicAdd(&g_agg2[8*j+2], xi4.z);
    atomicAdd(&g_agg2[8*j+3], xi4.w);
    atomicAdd(&g_agg2[8*j+4], xi4e);
}

// ---------------- K4: fused gc2 + leaky + fc1 + leaky ----------------------
// smem layout: w0b[0..99] b0b[100..119] w1b[120..219] b1b[220..239]
//              fc1_w[240..439] fc1_b[440..449]
__global__ void k4_vert2_fc1(const float* __restrict__ w0b, const float* __restrict__ b0b,
                             const float* __restrict__ w1b, const float* __restrict__ b1b,
                             const float* __restrict__ fc1_w, const float* __restrict__ fc1_b) {
    __shared__ float s[450];
    int t = threadIdx.x;
    if (t < 100) { s[t] = w0b[t]; s[120 + t] = w1b[t]; }
    if (t < 20)  { s[100 + t] = b0b[t]; s[220 + t] = b1b[t]; }
    if (t < 200) { s[240 + t] = fc1_w[t]; }
    if (t < 10)  { s[440 + t] = fc1_b[t]; }
    __syncthreads();

    int v = blockIdx.x * blockDim.x + threadIdx.x;
    if (v >= NV) return;

    float xv[5], av[5];
    float4 x4 = *(const float4*)&g_x1[8*v];
    xv[0]=x4.x; xv[1]=x4.y; xv[2]=x4.z; xv[3]=x4.w; xv[4]=g_x1[8*v+4];
    float4 g4 = *(const float4*)&g_agg2[8*v];
    av[0]=g4.x; av[1]=g4.y; av[2]=g4.z; av[3]=g4.w; av[4]=g_agg2[8*v+4];
    float dg = (float)g_deg[v];

    float x2[20];
#pragma unroll
    for (int k = 0; k < 20; k++) {
        float tt = s[100 + k] + dg * s[220 + k];
#pragma unroll
        for (int c = 0; c < 5; c++)
            tt += s[k*5 + c] * xv[c] + s[120 + k*5 + c] * av[c];
        x2[k] = leaky(tt);
    }
#pragma unroll
    for (int m = 0; m < 10; m += 2) {
        float t0 = s[440 + m], t1 = s[441 + m];
#pragma unroll
        for (int k = 0; k < 20; k++) {
            t0 += s[240 + m*20 + k]      * x2[k];
            t1 += s[240 + (m+1)*20 + k]  * x2[k];
        }
        float2 o = make_float2(leaky(t0), leaky(t1));
        *(float2*)&g_h[v*10 + m] = o;
    }
}

// ---------------- K5: fc2 GEMM  logits[b,o] = h[b,:]·w[o,:]  ---------------
// Grid: (NCHUNK, 4). Block 256 threads, 64 o x 64 b tile, split-K + atomics.
#define KSUB 32
#define CHUNK 1184   // 37*32
#define NCHUNK 50    // 50*1184 = 59200 >= 58500

__global__ void k5_fc2(const float* __restrict__ w) {
    __shared__ float sw[64*33];
    __shared__ float sh[64*33];
    int tid = threadIdx.x;
    int oq = tid & 15;     // o quad -> outputs oq*4 .. oq*4+3
    int bq = tid >> 4;     // b quad -> rows   bq*4 .. bq*4+3 (within btile)
    int btile = blockIdx.y;           // 0..3 -> 64 meshes each
    int kbeg = blockIdx.x * CHUNK;
    int kend = kbeg + CHUNK; if (kend > KDIM) kend = KDIM;

    float acc[4][4];
#pragma unroll
    for (int a = 0; a < 4; a++)
#pragma unroll
        for (int c = 0; c < 4; c++) acc[a][c] = 0.f;

    for (int k0 = kbeg; k0 < kend; k0 += KSUB) {
#pragma unroll
        for (int it = 0; it < 8; it++) {
            int lin = tid + it * 256;
            int row = lin >> 5, col = lin & 31;
            int k = k0 + col;
            bool ok = k < kend;
            sw[row*33 + col] = ok ? __ldg(w + (size_t)row * KDIM + k) : 0.f;
            sh[row*33 + col] = ok ? g_h[(size_t)(btile*64 + row) * KDIM + k] : 0.f;
        }
        __syncthreads();
#pragma unroll 4
        for (int kk = 0; kk < KSUB; kk++) {
            float wv[4], hv[4];
#pragma unroll
            for (int q = 0; q < 4; q++) wv[q] = sw[(oq*4 + q)*33 + kk];
#pragma unroll
            for (int q = 0; q < 4; q++) hv[q] = sh[(bq*4 + q)*33 + kk];
#pragma unroll
            for (int a = 0; a < 4; a++)
#pragma unroll
                for (int c = 0; c < 4; c++)
                    acc[a][c] += hv[a] * wv[c];
        }
        __syncthreads();
    }
#pragma unroll
    for (int a = 0; a < 4; a++)
#pragma unroll
        for (int c = 0; c < 4; c++)
            atomicAdd(&g_logits[(btile*64 + bq*4 + a) * NOUT + (oq*4 + c)], acc[a][c]);
}

// ---------------- K6: bias + softmax over 64 -------------------------------
__global__ void k6_softmax(const float* __restrict__ fc2_b, float* __restrict__ out) {
    int b = blockIdx.x;
    int t = threadIdx.x;  // 64
    __shared__ float s[64];
    float x = g_logits[b*NOUT + t] + fc2_b[t];
    s[t] = x; __syncthreads();
#pragma unroll
    for (int off = 32; off > 0; off >>= 1) {
        if (t < off) s[t] = fmaxf(s[t], s[t + off]);
        __syncthreads();
    }
    float m = s[0];
    __syncthreads();
    float e = expf(x - m);
    s[t] = e; __syncthreads();
#pragma unroll
    for (int off = 32; off > 0; off >>= 1) {
        if (t < off) s[t] = s[t] + s[t + off];
        __syncthreads();
    }
    float sum = s[0];
    out[b*NOUT + t] = e / sum;
}

// ---------------- launch ----------------------------------------------------
extern "C" void kernel_launch(void* const* d_in, const int* in_sizes, int n_in,
                              void* d_out, int out_size) {
    const float* verts = (const float*)d_in[0];
    const int*   edges = (const int*)  d_in[1];   // int32 (jax default, x64 off)
    const float* w0a = (const float*)d_in[2];
    const float* b0a = (const float*)d_in[3];
    const float* w1a = (const float*)d_in[4];
    const float* b1a = (const float*)d_in[5];
    const float* w0b = (const float*)d_in[6];
    const float* b0b = (const float*)d_in[7];
    const float* w1b = (const float*)d_in[8];
    const float* b1b = (const float*)d_in[9];
    const float* fc1_w = (const float*)d_in[10];
    const float* fc1_b = (const float*)d_in[11];
    const float* fc2_w = (const float*)d_in[12];
    const float* fc2_b = (const float*)d_in[13];
    float* out = (float*)d_out;

    void *p_deg, *p_agg1, *p_agg2, *p_logits;
    cudaGetSymbolAddress(&p_deg,    g_deg);
    cudaGetSymbolAddress(&p_agg1,   g_agg1);
    cudaGetSymbolAddress(&p_agg2,   g_agg2);
    cudaGetSymbolAddress(&p_logits, g_logits);
    cudaMemsetAsync(p_deg,    0, sizeof(int)   * NV,        0);
    cudaMemsetAsync(p_agg1,   0, sizeof(float) * NV * 4,    0);
    cudaMemsetAsync(p_agg2,   0, sizeof(float) * NV * 8,    0);
    cudaMemsetAsync(p_logits, 0, sizeof(float) * BATCH*NOUT,0);

    const int TB = 256;
    int eblocks = (NE + TB - 1) / TB;
    int vblocks = (NV + TB - 1) / TB;

    k1_edge_agg1<<<eblocks, TB>>>(edges, verts);
    k2_vert1    <<<vblocks, TB>>>(verts, w0a, b0a, w1a, b1a);
    k3_edge_agg2<<<eblocks, TB>>>(edges);
    k4_vert2_fc1<<<vblocks, TB>>>(w0b, b0b, w1b, b1b, fc1_w, fc1_b);
    dim3 g5(NCHUNK, 4);
    k5_fc2      <<<g5, 256>>>(fc2_w);
    k6_softmax  <<<BATCH, 64>>>(fc2_b, out);
}

// round 3
// speedup vs baseline: 1.6730x; 1.6730x over previous
#include <cuda_runtime.h>
#include <cuda_bf16.h>

// Problem constants
#define BATCH 256
#define VPM   5850
#define NV    (BATCH*VPM)      // 1,497,600 vertices
#define NE    (3*NV)           // 4,492,800 edges
#define KDIM  (VPM*10)         // 58,500
#define NOUT  64
#define NEG_SLOPE 0.01f

// ---------------- scratch (device globals: allocation-free) ----------------
__device__ float g_vp[NV*4];           // 24 MB padded verts (xyz,0)
__device__ float g_agg1[NV*4];         // 24 MB (xyz aggregate, w = degree)
__device__ float g_x1[NV*8];           // 48 MB (5 used, padded to 8)
__device__ float g_agg2[NV*8];         // 48 MB (5 used, padded to 8)
__device__ float g_h[NV*10];           // 60 MB  == (B, 58500) row-major
__device__ float g_logits[BATCH*NOUT]; // 64 KB

__device__ __forceinline__ float leaky(float t) {
    return t >= 0.f ? t : NEG_SLOPE * t;
}

// sm_90+ vectorized global reductions (no return value -> REDG)
__device__ __forceinline__ void red_add_v4(float* addr, float4 v) {
    asm volatile("red.global.add.v4.f32 [%0], {%1,%2,%3,%4};"
                 :: "l"(addr), "f"(v.x), "f"(v.y), "f"(v.z), "f"(v.w) : "memory");
}
__device__ __forceinline__ void red_add_f32(float* addr, float v) {
    asm volatile("red.global.add.f32 [%0], %1;"
                 :: "l"(addr), "f"(v) : "memory");
}

// ---------------- K0: pad verts to float4 ----------------------------------
__global__ void k0_pad(const float* __restrict__ verts) {
    int v = blockIdx.x * blockDim.x + threadIdx.x;
    if (v >= NV) return;
    float4 o = make_float4(verts[3*v+0], verts[3*v+1], verts[3*v+2], 0.f);
    *(float4*)&g_vp[4*v] = o;
}

// ---------------- K1: edge pass 1 — aggregate raw verts + degree -----------
// g_agg1[4i+0..2] += verts[j], g_agg1[4i+3] += 1  (and symmetric)
__global__ void k1_edge_agg1(const int* __restrict__ edges) {
    int e = blockIdx.x * blockDim.x + threadIdx.x;
    if (e >= NE) return;
    int2 ep = __ldg(((const int2*)edges) + e);
    float4 vi = __ldg((const float4*)&g_vp[4*ep.x]);
    float4 vj = __ldg((const float4*)&g_vp[4*ep.y]);
    vi.w = 1.f; vj.w = 1.f;
    red_add_v4(&g_agg1[4*ep.x], vj);
    red_add_v4(&g_agg1[4*ep.y], vi);
}

// ---------------- K2: vertex pass 1 — x1 = leaky(gc1) ----------------------
__global__ void k2_vert1(const float* __restrict__ verts,
                         const float* __restrict__ w0a, const float* __restrict__ b0a,
                         const float* __restrict__ w1a, const float* __restrict__ b1a) {
    int v = blockIdx.x * blockDim.x + threadIdx.x;
    if (v >= NV) return;
    float p[3], a[3];
    float4 p4 = __ldg((const float4*)&g_vp[4*v]);
    p[0] = p4.x; p[1] = p4.y; p[2] = p4.z;
    float4 a4 = *(const float4*)&g_agg1[4*v];
    a[0] = a4.x; a[1] = a4.y; a[2] = a4.z;
    float dg = a4.w;   // degree folded into the aggregate
    float x[5];
#pragma unroll
    for (int k = 0; k < 5; k++) {
        float t = __ldg(b0a + k) + dg * __ldg(b1a + k);
#pragma unroll
        for (int c = 0; c < 3; c++)
            t += __ldg(w0a + k*3 + c) * p[c] + __ldg(w1a + k*3 + c) * a[c];
        x[k] = leaky(t);
    }
    float4 o0 = make_float4(x[0], x[1], x[2], x[3]);
    float4 o1 = make_float4(x[4], 0.f, 0.f, 0.f);
    *(float4*)&g_x1[8*v]     = o0;
    *(float4*)&g_x1[8*v + 4] = o1;
}

// ---------------- K3: edge pass 2 — aggregate x1 ---------------------------
__global__ void k3_edge_agg2(const int* __restrict__ edges) {
    int e = blockIdx.x * blockDim.x + threadIdx.x;
    if (e >= NE) return;
    int2 ep = __ldg(((const int2*)edges) + e);
    int i = ep.x, j = ep.y;
    float4 xj4 = __ldg((const float4*)&g_x1[8*j]);
    float  xje = __ldg(&g_x1[8*j + 4]);
    float4 xi4 = __ldg((const float4*)&g_x1[8*i]);
    float  xie = __ldg(&g_x1[8*i + 4]);
    red_add_v4 (&g_agg2[8*i],     xj4);
    red_add_f32(&g_agg2[8*i + 4], xje);
    red_add_v4 (&g_agg2[8*j],     xi4);
    red_add_f32(&g_agg2[8*j + 4], xie);
}

// ---------------- K4: fused gc2 + leaky + fc1 + leaky ----------------------
__global__ void k4_vert2_fc1(const float* __restrict__ w0b, const float* __restrict__ b0b,
                             const float* __restrict__ w1b, const float* __restrict__ b1b,
                             const float* __restrict__ fc1_w, const float* __restrict__ fc1_b) {
    __shared__ float s[450];
    int t = threadIdx.x;
    if (t < 100) { s[t] = w0b[t]; s[120 + t] = w1b[t]; }
    if (t < 20)  { s[100 + t] = b0b[t]; s[220 + t] = b1b[t]; }
    if (t < 200) { s[240 + t] = fc1_w[t]; }
    if (t < 10)  { s[440 + t] = fc1_b[t]; }
    __syncthreads();

    int v = blockIdx.x * blockDim.x + threadIdx.x;
    if (v >= NV) return;

    float xv[5], av[5];
    float4 x4 = *(const float4*)&g_x1[8*v];
    xv[0]=x4.x; xv[1]=x4.y; xv[2]=x4.z; xv[3]=x4.w; xv[4]=g_x1[8*v+4];
    float4 g4 = *(const float4*)&g_agg2[8*v];
    av[0]=g4.x; av[1]=g4.y; av[2]=g4.z; av[3]=g4.w; av[4]=g_agg2[8*v+4];
    float dg = g_agg1[4*v + 3];

    float x2[20];
#pragma unroll
    for (int k = 0; k < 20; k++) {
        float tt = s[100 + k] + dg * s[220 + k];
#pragma unroll
        for (int c = 0; c < 5; c++)
            tt += s[k*5 + c] * xv[c] + s[120 + k*5 + c] * av[c];
        x2[k] = leaky(tt);
    }
#pragma unroll
    for (int m = 0; m < 10; m += 2) {
        float t0 = s[440 + m], t1 = s[441 + m];
#pragma unroll
        for (int k = 0; k < 20; k++) {
            t0 += s[240 + m*20 + k]      * x2[k];
            t1 += s[240 + (m+1)*20 + k]  * x2[k];
        }
        float2 o = make_float2(leaky(t0), leaky(t1));
        *(float2*)&g_h[v*10 + m] = o;
    }
}

// ---------------- K5: fc2 GEMM  logits[b,o] = h[b,:]·w[o,:]  ---------------
// Grid: (NCHUNK, 4). Block 256 threads, 64 o x 64 b tile, split-K + atomics.
#define KSUB 32
#define CHUNK 608    // 19*32
#define NCHUNK 97    // 97*608 = 58976 >= 58500

__global__ void k5_fc2(const float* __restrict__ w) {
    __shared__ float sw[64*33];
    __shared__ float sh[64*33];
    int tid = threadIdx.x;
    int oq = tid & 15;     // o quad -> outputs oq*4 .. oq*4+3
    int bq = tid >> 4;     // b quad -> rows   bq*4 .. bq*4+3 (within btile)
    int btile = blockIdx.y;           // 0..3 -> 64 meshes each
    int kbeg = blockIdx.x * CHUNK;
    int kend = kbeg + CHUNK; if (kend > KDIM) kend = KDIM;

    float acc[4][4];
#pragma unroll
    for (int a = 0; a < 4; a++)
#pragma unroll
        for (int c = 0; c < 4; c++) acc[a][c] = 0.f;

    for (int k0 = kbeg; k0 < kend; k0 += KSUB) {
#pragma unroll
        for (int it = 0; it < 8; it++) {
            int lin = tid + it * 256;
            int row = lin >> 5, col = lin & 31;
            int k = k0 + col;
            bool ok = k < kend;
            sw[row*33 + col] = ok ? __ldg(w + (size_t)row * KDIM + k) : 0.f;
            sh[row*33 + col] = ok ? __ldg(&g_h[(size_t)(btile*64 + row) * KDIM + k]) : 0.f;
        }
        __syncthreads();
#pragma unroll 4
        for (int kk = 0; kk < KSUB; kk++) {
            float wv[4], hv[4];
#pragma unroll
            for (int q = 0; q < 4; q++) wv[q] = sw[(oq*4 + q)*33 + kk];
#pragma unroll
            for (int q = 0; q < 4; q++) hv[q] = sh[(bq*4 + q)*33 + kk];
#pragma unroll
            for (int a = 0; a < 4; a++)
#pragma unroll
                for (int c = 0; c < 4; c++)
                    acc[a][c] += hv[a] * wv[c];
        }
        __syncthreads();
    }
#pragma unroll
    for (int a = 0; a < 4; a++)
#pragma unroll
        for (int c = 0; c < 4; c++)
            atomicAdd(&g_logits[(btile*64 + bq*4 + a) * NOUT + (oq*4 + c)], acc[a][c]);
}

// ---------------- K6: bias + softmax over 64 -------------------------------
__global__ void k6_softmax(const float* __restrict__ fc2_b, float* __restrict__ out) {
    int b = blockIdx.x;
    int t = threadIdx.x;  // 64
    __shared__ float s[64];
    float x = g_logits[b*NOUT + t] + fc2_b[t];
    s[t] = x; __syncthreads();
#pragma unroll
    for (int off = 32; off > 0; off >>= 1) {
        if (t < off) s[t] = fmaxf(s[t], s[t + off]);
        __syncthreads();
    }
    float m = s[0];
    __syncthreads();
    float e = expf(x - m);
    s[t] = e; __syncthreads();
#pragma unroll
    for (int off = 32; off > 0; off >>= 1) {
        if (t < off) s[t] = s[t] + s[t + off];
        __syncthreads();
    }
    float sum = s[0];
    out[b*NOUT + t] = e / sum;
}

// ---------------- launch ----------------------------------------------------
extern "C" void kernel_launch(void* const* d_in, const int* in_sizes, int n_in,
                              void* d_out, int out_size) {
    const float* verts = (const float*)d_in[0];
    const int*   edges = (const int*)  d_in[1];   // int32
    const float* w0a = (const float*)d_in[2];
    const float* b0a = (const float*)d_in[3];
    const float* w1a = (const float*)d_in[4];
    const float* b1a = (const float*)d_in[5];
    const float* w0b = (const float*)d_in[6];
    const float* b0b = (const float*)d_in[7];
    const float* w1b = (const float*)d_in[8];
    const float* b1b = (const float*)d_in[9];
    const float* fc1_w = (const float*)d_in[10];
    const float* fc1_b = (const float*)d_in[11];
    const float* fc2_w = (const float*)d_in[12];
    const float* fc2_b = (const float*)d_in[13];
    float* out = (float*)d_out;

    void *p_agg1, *p_agg2, *p_logits;
    cudaGetSymbolAddress(&p_agg1,   g_agg1);
    cudaGetSymbolAddress(&p_agg2,   g_agg2);
    cudaGetSymbolAddress(&p_logits, g_logits);
    cudaMemsetAsync(p_agg1,   0, sizeof(float) * NV * 4,     0);
    cudaMemsetAsync(p_agg2,   0, sizeof(float) * NV * 8,     0);
    cudaMemsetAsync(p_logits, 0, sizeof(float) * BATCH*NOUT, 0);

    const int TB = 256;
    int eblocks = (NE + TB - 1) / TB;
    int vblocks = (NV + TB - 1) / TB;

    k0_pad      <<<vblocks, TB>>>(verts);
    k1_edge_agg1<<<eblocks, TB>>>(edges);
    k2_vert1    <<<vblocks, TB>>>(verts, w0a, b0a, w1a, b1a);
    k3_edge_agg2<<<eblocks, TB>>>(edges);
    k4_vert2_fc1<<<vblocks, TB>>>(w0b, b0b, w1b, b1b, fc1_w, fc1_b);
    dim3 g5(NCHUNK, 4);
    k5_fc2      <<<g5, 256>>>(fc2_w);
    k6_softmax  <<<BATCH, 64>>>(fc2_b, out);
}

// round 4
// speedup vs baseline: 2.1149x; 1.2641x over previous
#include <cuda_runtime.h>
#include <cuda_fp16.h>
#include <cuda_bf16.h>

// Problem constants
#define BATCH 256
#define VPM   5850
#define NV    (BATCH*VPM)      // 1,497,600 vertices
#define NE    (3*NV)           // 4,492,800 edges
#define KDIM  (VPM*10)         // 58,500
#define NOUT  64
#define NEG_SLOPE 0.01f

typedef unsigned long long ull;
typedef unsigned int uint;

// ---------------- scratch (device globals: allocation-free) ----------------
__device__ float g_vp[NV*4];           // 24 MB padded verts (xyz,0)
__device__ float g_agg1[NV*4];         // 24 MB (xyz aggregate, w = degree)
__device__ uint4 g_x1h[NV];            // 24 MB x1 as 8 fp16 (5 used)
__device__ uint4 g_agg2h[NV];          // 24 MB agg2 as 8 fp16 (5 used)
__device__ float g_h[NV*10];           // 60 MB  == (B, 58500) row-major
__device__ float g_logits[BATCH*NOUT]; // 64 KB

__device__ __forceinline__ float leaky(float t) {
    return t >= 0.f ? t : NEG_SLOPE * t;
}

// ---------------- f32x2 packed-FMA helpers (2x fp32 FMA throughput) --------
__device__ __forceinline__ void ffma2(ull& d, ull a, ull b) {
    asm("fma.rn.f32x2 %0, %1, %2, %0;" : "+l"(d) : "l"(a), "l"(b));
}
__device__ __forceinline__ ull pack2(float lo, float hi) {
    ull r; asm("mov.b64 %0, {%1,%2};" : "=l"(r) : "f"(lo), "f"(hi)); return r;
}
__device__ __forceinline__ float2 unpack2(ull v) {
    float2 r; asm("mov.b64 {%0,%1}, %2;" : "=f"(r.x), "=f"(r.y) : "l"(v)); return r;
}

// ---------------- vectorized global reductions ------------------------------
__device__ __forceinline__ void red_add_v4f32(float* addr, float4 v) {
    asm volatile("red.global.add.v4.f32 [%0], {%1,%2,%3,%4};"
                 :: "l"(addr), "f"(v.x), "f"(v.y), "f"(v.z), "f"(v.w) : "memory");
}
__device__ __forceinline__ void red_add_v4f16x2(uint4* addr, uint4 v) {
    asm volatile("red.global.add.noftz.v4.f16x2 [%0], {%1,%2,%3,%4};"
                 :: "l"(addr), "r"(v.x), "r"(v.y), "r"(v.z), "r"(v.w) : "memory");
}

// ---------------- K0: pad verts to float4 ----------------------------------
__global__ void k0_pad(const float* __restrict__ verts) {
    int v = blockIdx.x * blockDim.x + threadIdx.x;
    if (v >= NV) return;
    float4 o = make_float4(verts[3*v+0], verts[3*v+1], verts[3*v+2], 0.f);
    *(float4*)&g_vp[4*v] = o;
}

// ---------------- K1: edge pass 1 — aggregate raw verts + degree -----------
__global__ void k1_edge_agg1(const int* __restrict__ edges) {
    int e = blockIdx.x * blockDim.x + threadIdx.x;
    if (e >= NE) return;
    int2 ep = __ldg(((const int2*)edges) + e);
    float4 vi = __ldg((const float4*)&g_vp[4*ep.x]);
    float4 vj = __ldg((const float4*)&g_vp[4*ep.y]);
    vi.w = 1.f; vj.w = 1.f;
    red_add_v4f32(&g_agg1[4*ep.x], vj);
    red_add_v4f32(&g_agg1[4*ep.y], vi);
}

// ---------------- K2: vertex pass 1 — x1 = leaky(gc1), store fp16 ----------
__global__ void k2_vert1(const float* __restrict__ w0a, const float* __restrict__ b0a,
                         const float* __restrict__ w1a, const float* __restrict__ b1a) {
    int v = blockIdx.x * blockDim.x + threadIdx.x;
    if (v >= NV) return;
    float4 p4 = __ldg((const float4*)&g_vp[4*v]);
    float4 a4 = *(const float4*)&g_agg1[4*v];
    float p[3] = {p4.x, p4.y, p4.z};
    float a[3] = {a4.x, a4.y, a4.z};
    float dg = a4.w;   // degree folded into the aggregate
    float x[5];
#pragma unroll
    for (int k = 0; k < 5; k++) {
        float t = __ldg(b0a + k) + dg * __ldg(b1a + k);
#pragma unroll
        for (int c = 0; c < 3; c++)
            t += __ldg(w0a + k*3 + c) * p[c] + __ldg(w1a + k*3 + c) * a[c];
        x[k] = leaky(t);
    }
    __half2 p01 = __floats2half2_rn(x[0], x[1]);
    __half2 p23 = __floats2half2_rn(x[2], x[3]);
    __half2 p4z = __floats2half2_rn(x[4], 0.f);
    uint4 o;
    o.x = *(uint*)&p01; o.y = *(uint*)&p23; o.z = *(uint*)&p4z; o.w = 0u;
    g_x1h[v] = o;
}

// ---------------- K3: edge pass 2 — aggregate x1 (fp16, 4 L2 ops/edge) -----
__global__ void k3_edge_agg2(const int* __restrict__ edges) {
    int e = blockIdx.x * blockDim.x + threadIdx.x;
    if (e >= NE) return;
    int2 ep = __ldg(((const int2*)edges) + e);
    uint4 xj = __ldg(&g_x1h[ep.y]);
    uint4 xi = __ldg(&g_x1h[ep.x]);
    red_add_v4f16x2(&g_agg2h[ep.x], xj);
    red_add_v4f16x2(&g_agg2h[ep.y], xi);
}

// ---------------- K4: fused gc2 + leaky + fc1 + leaky (f32x2) --------------
__global__ void k4_vert2_fc1(const float* __restrict__ w0b, const float* __restrict__ b0b,
                             const float* __restrict__ w1b, const float* __restrict__ b1b,
                             const float* __restrict__ fc1_w, const float* __restrict__ fc1_b) {
    __shared__ float2 sAB[100];   // (w0b[k][c], w1b[k][c]) at k*5+c
    __shared__ float2 sF[100];    // (fc1_w[m][2q], fc1_w[m][2q+1]) at m*10+q
    __shared__ float  sb0[20], sb1[20], sfb[10];
    int t = threadIdx.x;
    if (t < 100) {
        sAB[t] = make_float2(w0b[t], w1b[t]);
        sF[t]  = ((const float2*)fc1_w)[t];
    }
    if (t < 20) { sb0[t] = b0b[t]; sb1[t] = b1b[t]; }
    if (t < 10) { sfb[t] = fc1_b[t]; }
    __syncthreads();

    int v = blockIdx.x * blockDim.x + threadIdx.x;
    if (v >= NV) return;

    uint4 xr = g_x1h[v];
    uint4 ar = g_agg2h[v];
    float2 x01 = __half22float2(*reinterpret_cast<__half2*>(&xr.x));
    float2 x23 = __half22float2(*reinterpret_cast<__half2*>(&xr.y));
    float2 x4_ = __half22float2(*reinterpret_cast<__half2*>(&xr.z));
    float2 a01 = __half22float2(*reinterpret_cast<__half2*>(&ar.x));
    float2 a23 = __half22float2(*reinterpret_cast<__half2*>(&ar.y));
    float2 a4_ = __half22float2(*reinterpret_cast<__half2*>(&ar.z));
    float xv[5] = {x01.x, x01.y, x23.x, x23.y, x4_.x};
    float av[5] = {a01.x, a01.y, a23.x, a23.y, a4_.x};
    float dg = g_agg1[4*v + 3];

    ull xa[5];
#pragma unroll
    for (int c = 0; c < 5; c++) xa[c] = pack2(xv[c], av[c]);

    float x2[20];
#pragma unroll
    for (int k = 0; k < 20; k++) {
        ull acc = pack2(fmaf(dg, sb1[k], sb0[k]), 0.f);
#pragma unroll
        for (int c = 0; c < 5; c++)
            ffma2(acc, xa[c], *(const ull*)&sAB[k*5 + c]);
        float2 r = unpack2(acc);
        x2[k] = leaky(r.x + r.y);
    }

    ull x2p[10];
#pragma unroll
    for (int q = 0; q < 10; q++) x2p[q] = pack2(x2[2*q], x2[2*q+1]);

    float hm[10];
#pragma unroll
    for (int m = 0; m < 10; m++) {
        ull acc = pack2(sfb[m], 0.f);
#pragma unroll
        for (int q = 0; q < 10; q++)
            ffma2(acc, x2p[q], *(const ull*)&sF[m*10 + q]);
        float2 r = unpack2(acc);
        hm[m] = leaky(r.x + r.y);
    }
#pragma unroll
    for (int m = 0; m < 10; m += 2)
        *(float2*)&g_h[(size_t)v*10 + m] = make_float2(hm[m], hm[m+1]);
}

// ---------------- K5: fc2 GEMM with f32x2 ----------------------------------
// Grid: (NCHUNK, 4). Block 256, 64o x 64b tile, 4x4/thread, split-K atomics.
#define KSUB 32
#define CHUNK 608    // 19*32
#define NCHUNK 97    // 97*608 = 58976 >= 58500
#define SWP 66       // sw row pad (even -> 8B-aligned LDS.64)

__global__ void k5_fc2(const float* __restrict__ w) {
    __shared__ float sw[KSUB*SWP];   // [kk][o]  transposed weight tile
    __shared__ float sh[64*33];      // [row][kk]
    int tid = threadIdx.x;
    int oq = tid & 15;     // outputs oq*4 .. oq*4+3
    int bq = tid >> 4;     // rows    bq*4 .. bq*4+3 within btile
    int btile = blockIdx.y;
    int kbeg = blockIdx.x * CHUNK;
    int kend = kbeg + CHUNK; if (kend > KDIM) kend = KDIM;

    ull acc[4][2];
#pragma unroll
    for (int a = 0; a < 4; a++) { acc[a][0] = 0ull; acc[a][1] = 0ull; }

    for (int k0 = kbeg; k0 < kend; k0 += KSUB) {
#pragma unroll
        for (int it = 0; it < 8; it++) {
            int lin = tid + it * 256;
            int row = lin >> 5, col = lin & 31;
            int k = k0 + col;
            bool ok = k < kend;
            sw[col*SWP + row] = ok ? __ldg(w + (size_t)row * KDIM + k) : 0.f;
            sh[row*33 + col]  = ok ? __ldg(&g_h[(size_t)(btile*64 + row) * KDIM + k]) : 0.f;
        }
        __syncthreads();
#pragma unroll 4
        for (int kk = 0; kk < KSUB; kk++) {
            ull w01 = *(const ull*)&sw[kk*SWP + oq*4];
            ull w23 = *(const ull*)&sw[kk*SWP + oq*4 + 2];
#pragma unroll
            for (int a = 0; a < 4; a++) {
                float hv = sh[(bq*4 + a)*33 + kk];
                ull h2 = pack2(hv, hv);
                ffma2(acc[a][0], h2, w01);
                ffma2(acc[a][1], h2, w23);
            }
        }
        __syncthreads();
    }
#pragma unroll
    for (int a = 0; a < 4; a++) {
        float2 r0 = unpack2(acc[a][0]);
        float2 r1 = unpack2(acc[a][1]);
        float* dst = &g_logits[(btile*64 + bq*4 + a) * NOUT + oq*4];
        atomicAdd(dst + 0, r0.x);
        atomicAdd(dst + 1, r0.y);
        atomicAdd(dst + 2, r1.x);
        atomicAdd(dst + 3, r1.y);
    }
}

// ---------------- K6: bias + softmax over 64 -------------------------------
__global__ void k6_softmax(const float* __restrict__ fc2_b, float* __restrict__ out) {
    int b = blockIdx.x;
    int t = threadIdx.x;  // 64
    __shared__ float s[64];
    float x = g_logits[b*NOUT + t] + fc2_b[t];
    s[t] = x; __syncthreads();
#pragma unroll
    for (int off = 32; off > 0; off >>= 1) {
        if (t < off) s[t] = fmaxf(s[t], s[t + off]);
        __syncthreads();
    }
    float m = s[0];
    __syncthreads();
    float e = expf(x - m);
    s[t] = e; __syncthreads();
#pragma unroll
    for (int off = 32; off > 0; off >>= 1) {
        if (t < off) s[t] = s[t] + s[t + off];
        __syncthreads();
    }
    float sum = s[0];
    out[b*NOUT + t] = e / sum;
}

// ---------------- launch ----------------------------------------------------
extern "C" void kernel_launch(void* const* d_in, const int* in_sizes, int n_in,
                              void* d_out, int out_size) {
    const float* verts = (const float*)d_in[0];
    const int*   edges = (const int*)  d_in[1];   // int32
    const float* w0a = (const float*)d_in[2];
    const float* b0a = (const float*)d_in[3];
    const float* w1a = (const float*)d_in[4];
    const float* b1a = (const float*)d_in[5];
    const float* w0b = (const float*)d_in[6];
    const float* b0b = (const float*)d_in[7];
    const float* w1b = (const float*)d_in[8];
    const float* b1b = (const float*)d_in[9];
    const float* fc1_w = (const float*)d_in[10];
    const float* fc1_b = (const float*)d_in[11];
    const float* fc2_w = (const float*)d_in[12];
    const float* fc2_b = (const float*)d_in[13];
    float* out = (float*)d_out;

    void *p_agg1, *p_agg2, *p_logits;
    cudaGetSymbolAddress(&p_agg1,   g_agg1);
    cudaGetSymbolAddress(&p_agg2,   g_agg2h);
    cudaGetSymbolAddress(&p_logits, g_logits);
    cudaMemsetAsync(p_agg1,   0, sizeof(float) * NV * 4,     0);
    cudaMemsetAsync(p_agg2,   0, sizeof(uint4) * NV,         0);
    cudaMemsetAsync(p_logits, 0, sizeof(float) * BATCH*NOUT, 0);

    const int TB = 256;
    int eblocks = (NE + TB - 1) / TB;
    int vblocks = (NV + TB - 1) / TB;

    k0_pad      <<<vblocks, TB>>>(verts);
    k1_edge_agg1<<<eblocks, TB>>>(edges);
    k2_vert1    <<<vblocks, TB>>>(w0a, b0a, w1a, b1a);
    k3_edge_agg2<<<eblocks, TB>>>(edges);
    k4_vert2_fc1<<<vblocks, TB>>>(w0b, b0b, w1b, b1b, fc1_w, fc1_b);
    dim3 g5(NCHUNK, 4);
    k5_fc2      <<<g5, 256>>>(fc2_w);
    k6_softmax  <<<BATCH, 64>>>(fc2_b, out);
}

// round 5
// speedup vs baseline: 2.1900x; 1.0355x over previous
#include <cuda_runtime.h>
#include <cuda_fp16.h>
#include <cuda_bf16.h>

// Problem constants
#define BATCH 256
#define VPM   5850
#define NV    (BATCH*VPM)      // 1,497,600 vertices
#define NE    (3*NV)           // 4,492,800 edges
#define KDIM  (VPM*10)         // 58,500
#define NOUT  64
#define NEG_SLOPE 0.01f

typedef unsigned long long ull;
typedef unsigned int uint;

// ---------------- scratch (device globals: allocation-free) ----------------
__device__ uint2 g_vph[NV];            // 12 MB verts as 4 fp16 (x,y,z,1)
__device__ uint2 g_agg1h[NV];          // 12 MB (Sx,Sy,Sz,deg) fp16
__device__ uint4 g_x1h[NV];            // 24 MB x1 as 8 fp16 (5 used)
__device__ uint4 g_agg2h[NV];          // 24 MB agg2 as 8 fp16 (5 used)
__device__ float g_h[NV*10];           // 60 MB  == (B, 58500) row-major
__device__ float g_logits[BATCH*NOUT]; // 64 KB

__device__ __forceinline__ float leaky(float t) {
    return t >= 0.f ? t : NEG_SLOPE * t;
}

// ---------------- f32x2 packed-FMA helpers (2x fp32 FMA throughput) --------
__device__ __forceinline__ void ffma2(ull& d, ull a, ull b) {
    asm("fma.rn.f32x2 %0, %1, %2, %0;" : "+l"(d) : "l"(a), "l"(b));
}
__device__ __forceinline__ ull pack2(float lo, float hi) {
    ull r; asm("mov.b64 %0, {%1,%2};" : "=l"(r) : "f"(lo), "f"(hi)); return r;
}
__device__ __forceinline__ float2 unpack2(ull v) {
    float2 r; asm("mov.b64 {%0,%1}, %2;" : "=f"(r.x), "=f"(r.y) : "l"(v)); return r;
}

// ---------------- vectorized global reductions ------------------------------
__device__ __forceinline__ void red_add_v2f16x2(uint2* addr, uint2 v) {
    asm volatile("red.global.add.noftz.v2.f16x2 [%0], {%1,%2};"
                 :: "l"(addr), "r"(v.x), "r"(v.y) : "memory");
}
__device__ __forceinline__ void red_add_v4f16x2(uint4* addr, uint4 v) {
    asm volatile("red.global.add.noftz.v4.f16x2 [%0], {%1,%2,%3,%4};"
                 :: "l"(addr), "r"(v.x), "r"(v.y), "r"(v.z), "r"(v.w) : "memory");
}

// ---------------- K0: verts -> fp16x4 (x,y,z,1); zero agg1h ----------------
__global__ void k0_pad(const float* __restrict__ verts) {
    int v = blockIdx.x * blockDim.x + threadIdx.x;
    if (v >= NV) return;
    float vx = verts[3*v+0], vy = verts[3*v+1], vz = verts[3*v+2];
    __half2 lo = __floats2half2_rn(vx, vy);
    __half2 hi = __floats2half2_rn(vz, 1.0f);
    uint2 o; o.x = *(uint*)&lo; o.y = *(uint*)&hi;
    g_vph[v] = o;
    g_agg1h[v] = make_uint2(0u, 0u);
}

// ---------------- K1: edge pass 1 (8B gather + 8B red); zero agg2h ---------
__global__ void k1_edge_agg1(const int* __restrict__ edges) {
    int e = blockIdx.x * blockDim.x + threadIdx.x;
    if (e < NV) g_agg2h[e] = make_uint4(0u, 0u, 0u, 0u);   // fold memset
    if (e >= NE) return;
    int2 ep = __ldg(((const int2*)edges) + e);
    uint2 vi = __ldg(&g_vph[ep.x]);
    uint2 vj = __ldg(&g_vph[ep.y]);
    red_add_v2f16x2(&g_agg1h[ep.x], vj);
    red_add_v2f16x2(&g_agg1h[ep.y], vi);
}

// ---------------- K2: vertex pass 1 — x1 = leaky(gc1), store fp16 ----------
__global__ void k2_vert1(const float* __restrict__ verts,
                         const float* __restrict__ w0a, const float* __restrict__ b0a,
                         const float* __restrict__ w1a, const float* __restrict__ b1a) {
    int v = blockIdx.x * blockDim.x + threadIdx.x;
    if (v >= NV) return;
    float p[3];
    p[0] = verts[3*v+0]; p[1] = verts[3*v+1]; p[2] = verts[3*v+2];
    uint2 ar = g_agg1h[v];
    float2 a01 = __half22float2(*reinterpret_cast<__half2*>(&ar.x));
    float2 a2d = __half22float2(*reinterpret_cast<__half2*>(&ar.y));
    float a[3] = {a01.x, a01.y, a2d.x};
    float dg = a2d.y;   // degree (exact in fp16)
    float x[5];
#pragma unroll
    for (int k = 0; k < 5; k++) {
        float t = __ldg(b0a + k) + dg * __ldg(b1a + k);
#pragma unroll
        for (int c = 0; c < 3; c++)
            t += __ldg(w0a + k*3 + c) * p[c] + __ldg(w1a + k*3 + c) * a[c];
        x[k] = leaky(t);
    }
    __half2 p01 = __floats2half2_rn(x[0], x[1]);
    __half2 p23 = __floats2half2_rn(x[2], x[3]);
    __half2 p4z = __floats2half2_rn(x[4], 0.f);
    uint4 o;
    o.x = *(uint*)&p01; o.y = *(uint*)&p23; o.z = *(uint*)&p4z; o.w = 0u;
    g_x1h[v] = o;
}

// ---------------- K3: edge pass 2 — aggregate x1 (fp16, 4 L2 ops/edge) -----
__global__ void k3_edge_agg2(const int* __restrict__ edges) {
    int e = blockIdx.x * blockDim.x + threadIdx.x;
    if (e >= NE) return;
    int2 ep = __ldg(((const int2*)edges) + e);
    uint4 xj = __ldg(&g_x1h[ep.y]);
    uint4 xi = __ldg(&g_x1h[ep.x]);
    red_add_v4f16x2(&g_agg2h[ep.x], xj);
    red_add_v4f16x2(&g_agg2h[ep.y], xi);
}

// ---------------- K4: fused gc2 + leaky + fc1 + leaky (f32x2) --------------
__global__ void k4_vert2_fc1(const float* __restrict__ w0b, const float* __restrict__ b0b,
                             const float* __restrict__ w1b, const float* __restrict__ b1b,
                             const float* __restrict__ fc1_w, const float* __restrict__ fc1_b) {
    __shared__ float2 sAB[100];   // (w0b[k][c], w1b[k][c]) at k*5+c
    __shared__ float2 sF[100];    // (fc1_w[m][2q], fc1_w[m][2q+1]) at m*10+q
    __shared__ float  sb0[20], sb1[20], sfb[10];
    int t = threadIdx.x;
    if (t < 100) {
        sAB[t] = make_float2(w0b[t], w1b[t]);
        sF[t]  = ((const float2*)fc1_w)[t];
    }
    if (t < 20) { sb0[t] = b0b[t]; sb1[t] = b1b[t]; }
    if (t < 10) { sfb[t] = fc1_b[t]; }
    __syncthreads();

    int v = blockIdx.x * blockDim.x + threadIdx.x;
    if (v >= NV) return;
    if (v < BATCH*NOUT) g_logits[v] = 0.f;   // fold memset (k5 runs after)

    uint4 xr = g_x1h[v];
    uint4 ar = g_agg2h[v];
    float2 x01 = __half22float2(*reinterpret_cast<__half2*>(&xr.x));
    float2 x23 = __half22float2(*reinterpret_cast<__half2*>(&xr.y));
    float2 x4_ = __half22float2(*reinterpret_cast<__half2*>(&xr.z));
    float2 a01 = __half22float2(*reinterpret_cast<__half2*>(&ar.x));
    float2 a23 = __half22float2(*reinterpret_cast<__half2*>(&ar.y));
    float2 a4_ = __half22float2(*reinterpret_cast<__half2*>(&ar.z));
    float xv[5] = {x01.x, x01.y, x23.x, x23.y, x4_.x};
    float av[5] = {a01.x, a01.y, a23.x, a23.y, a4_.x};
    uint2 dr = g_agg1h[v];
    float dg = __half22float2(*reinterpret_cast<__half2*>(&dr.y)).y;

    ull xa[5];
#pragma unroll
    for (int c = 0; c < 5; c++) xa[c] = pack2(xv[c], av[c]);

    float x2[20];
#pragma unroll
    for (int k = 0; k < 20; k++) {
        ull acc = pack2(fmaf(dg, sb1[k], sb0[k]), 0.f);
#pragma unroll
        for (int c = 0; c < 5; c++)
            ffma2(acc, xa[c], *(const ull*)&sAB[k*5 + c]);
        float2 r = unpack2(acc);
        x2[k] = leaky(r.x + r.y);
    }

    ull x2p[10];
#pragma unroll
    for (int q = 0; q < 10; q++) x2p[q] = pack2(x2[2*q], x2[2*q+1]);

    float hm[10];
#pragma unroll
    for (int m = 0; m < 10; m++) {
        ull acc = pack2(sfb[m], 0.f);
#pragma unroll
        for (int q = 0; q < 10; q++)
            ffma2(acc, x2p[q], *(const ull*)&sF[m*10 + q]);
        float2 r = unpack2(acc);
        hm[m] = leaky(r.x + r.y);
    }
#pragma unroll
    for (int m = 0; m < 10; m += 2)
        *(float2*)&g_h[(size_t)v*10 + m] = make_float2(hm[m], hm[m+1]);
}

// ---------------- K5: fc2 GEMM with f32x2 + register double-buffer ---------
#define KSUB 32
#define CHUNK 608    // 19*32
#define NCHUNK 97    // 97*608 = 58976 >= 58500
#define SWP 66       // sw row pad (even -> 8B-aligned LDS.64)

__global__ void k5_fc2(const float* __restrict__ w) {
    __shared__ float sw[KSUB*SWP];   // [kk][o]  transposed weight tile
    __shared__ float sh[64*33];      // [row][kk]
    int tid = threadIdx.x;
    int oq = tid & 15;     // outputs oq*4 .. oq*4+3
    int bq = tid >> 4;     // rows    bq*4 .. bq*4+3 within btile
    int btile = blockIdx.y;
    int kbeg = blockIdx.x * CHUNK;
    int kend = kbeg + CHUNK; if (kend > KDIM) kend = KDIM;

    int lrow = tid >> 5, lcol = tid & 31;   // this thread's 8 load slots share lcol
    const float* wbase = w + (size_t)lrow * KDIM;
    const float* hbase = &g_h[(size_t)(btile*64 + lrow) * KDIM];

    ull acc[4][2];
#pragma unroll
    for (int a = 0; a < 4; a++) { acc[a][0] = 0ull; acc[a][1] = 0ull; }

    float rw[8], rh[8];
    // prologue: load first tile into registers
    {
        int k = kbeg + lcol;
        bool ok = k < kend;
#pragma unroll
        for (int it = 0; it < 8; it++) {
            rw[it] = ok ? __ldg(wbase + (size_t)(it*8) * KDIM + k) : 0.f;
            rh[it] = ok ? __ldg(hbase + (size_t)(it*8) * KDIM + k) : 0.f;
        }
    }

    for (int k0 = kbeg; k0 < kend; k0 += KSUB) {
#pragma unroll
        for (int it = 0; it < 8; it++) {
            int row = lrow + it*8;
            sw[lcol*SWP + row] = rw[it];
            sh[row*33 + lcol]  = rh[it];
        }
        __syncthreads();
        // prefetch next tile into registers (overlaps with compute)
        int kn = k0 + KSUB + lcol;
        if (k0 + KSUB < kend) {
            bool ok = kn < kend;
#pragma unroll
            for (int it = 0; it < 8; it++) {
                rw[it] = ok ? __ldg(wbase + (size_t)(it*8) * KDIM + kn) : 0.f;
                rh[it] = ok ? __ldg(hbase + (size_t)(it*8) * KDIM + kn) : 0.f;
            }
        }
#pragma unroll 4
        for (int kk = 0; kk < KSUB; kk++) {
            ull w01 = *(const ull*)&sw[kk*SWP + oq*4];
            ull w23 = *(const ull*)&sw[kk*SWP + oq*4 + 2];
#pragma unroll
            for (int a = 0; a < 4; a++) {
                float hv = sh[(bq*4 + a)*33 + kk];
                ull h2 = pack2(hv, hv);
                ffma2(acc[a][0], h2, w01);
                ffma2(acc[a][1], h2, w23);
            }
        }
        __syncthreads();
    }
#pragma unroll
    for (int a = 0; a < 4; a++) {
        float2 r0 = unpack2(acc[a][0]);
        float2 r1 = unpack2(acc[a][1]);
        float* dst = &g_logits[(btile*64 + bq*4 + a) * NOUT + oq*4];
        atomicAdd(dst + 0, r0.x);
        atomicAdd(dst + 1, r0.y);
        atomicAdd(dst + 2, r1.x);
        atomicAdd(dst + 3, r1.y);
    }
}

// ---------------- K6: bias + softmax over 64 -------------------------------
__global__ void k6_softmax(const float* __restrict__ fc2_b, float* __restrict__ out) {
    int b = blockIdx.x;
    int t = threadIdx.x;  // 64
    __shared__ float s[64];
    float x = g_logits[b*NOUT + t] + fc2_b[t];
    s[t] = x; __syncthreads();
#pragma unroll
    for (int off = 32; off > 0; off >>= 1) {
        if (t < off) s[t] = fmaxf(s[t], s[t + off]);
        __syncthreads();
    }
    float m = s[0];
    __syncthreads();
    float e = expf(x - m);
    s[t] = e; __syncthreads();
#pragma unroll
    for (int off = 32; off > 0; off >>= 1) {
        if (t < off) s[t] = s[t] + s[t + off];
        __syncthreads();
    }
    float sum = s[0];
    out[b*NOUT + t] = e / sum;
}

// ---------------- launch ----------------------------------------------------
extern "C" void kernel_launch(void* const* d_in, const int* in_sizes, int n_in,
                              void* d_out, int out_size) {
    const float* verts = (const float*)d_in[0];
    const int*   edges = (const int*)  d_in[1];   // int32
    const float* w0a = (const float*)d_in[2];
    const float* b0a = (const float*)d_in[3];
    const float* w1a = (const float*)d_in[4];
    const float* b1a = (const float*)d_in[5];
    const float* w0b = (const float*)d_in[6];
    const float* b0b = (const float*)d_in[7];
    const float* w1b = (const float*)d_in[8];
    const float* b1b = (const float*)d_in[9];
    const float* fc1_w = (const float*)d_in[10];
    const float* fc1_b = (const float*)d_in[11];
    const float* fc2_w = (const float*)d_in[12];
    const float* fc2_b = (const float*)d_in[13];
    float* out = (float*)d_out;

    const int TB = 256;
    int eblocks = (NE + TB - 1) / TB;
    int vblocks = (NV + TB - 1) / TB;

    k0_pad      <<<vblocks, TB>>>(verts);
    k1_edge_agg1<<<eblocks, TB>>>(edges);
    k2_vert1    <<<vblocks, TB>>>(verts, w0a, b0a, w1a, b1a);
    k3_edge_agg2<<<eblocks, TB>>>(edges);
    k4_vert2_fc1<<<vblocks, TB>>>(w0b, b0b, w1b, b1b, fc1_w, fc1_b);
    dim3 g5(NCHUNK, 4);
    k5_fc2      <<<g5, 256>>>(fc2_w);
    k6_softmax  <<<BATCH, 64>>>(fc2_b, out);
}

// round 6
// speedup vs baseline: 2.2982x; 1.0494x over previous
#include <cuda_runtime.h>
#include <cuda_fp16.h>
#include <cuda_bf16.h>

// Problem constants
#define BATCH 256
#define VPM   5850
#define NV    (BATCH*VPM)      // 1,497,600 vertices
#define NE    (3*NV)           // 4,492,800 edges
#define KDIM  (VPM*10)         // 58,500
#define NOUT  64
#define NEG_SLOPE 0.01f

#define VSCALE 8.0f            // fp8 scale for verts (and degree lane)
#define VINV   0.125f
#define XSCALE 32.0f           // fp8 scale for x1
#define XINV   0.03125f

typedef unsigned long long ull;
typedef unsigned int uint;
typedef unsigned short ushort;

// ---------------- scratch (device globals: allocation-free) ----------------
__device__ uint   g_v8[NV];            //  6 MB verts as e4m3x4 (8x,8y,8z,8)
__device__ uint2  g_agg1h[NV];         // 12 MB (8Sx,8Sy,8Sz,8deg) fp16
__device__ uint2  g_x18[NV];           // 12 MB x1 as e4m3x8 (32*x, 5 used)
__device__ uint4  g_x1h[NV];           // 24 MB x1 fp16 copy (exact path for k4)
__device__ uint4  g_agg2h[NV];         // 24 MB agg2 as 8 fp16 (5 used, 32x scale)
__device__ __half g_hh[(size_t)NV*10]; // 30 MB h fp16 == (B, 58500) row-major
__device__ float  g_logits[BATCH*NOUT];// 64 KB

__device__ __forceinline__ float leaky(float t) {
    return t >= 0.f ? t : NEG_SLOPE * t;
}

// ---------------- f32x2 packed-FMA helpers ----------------------------------
__device__ __forceinline__ void ffma2(ull& d, ull a, ull b) {
    asm("fma.rn.f32x2 %0, %1, %2, %0;" : "+l"(d) : "l"(a), "l"(b));
}
__device__ __forceinline__ ull pack2(float lo, float hi) {
    ull r; asm("mov.b64 %0, {%1,%2};" : "=l"(r) : "f"(lo), "f"(hi)); return r;
}
__device__ __forceinline__ float2 unpack2(ull v) {
    float2 r; asm("mov.b64 {%0,%1}, %2;" : "=f"(r.x), "=f"(r.y) : "l"(v)); return r;
}

// ---------------- fp8 encode/decode -----------------------------------------
// enc8(lo,hi): two f32 -> e4m3x2 (lo in low byte)
__device__ __forceinline__ ushort enc8(float lo, float hi) {
    ushort r;
    asm("cvt.rn.satfinite.e4m3x2.f32 %0, %1, %2;" : "=h"(r) : "f"(hi), "f"(lo));
    return r;
}
// dec8: e4m3x2 -> f16x2 (low byte -> low half)
__device__ __forceinline__ uint dec8(uint v) {
    uint r;
    asm("cvt.rn.f16x2.e4m3x2 %0, %1;" : "=r"(r) : "h"((ushort)v));
    return r;
}

// ---------------- vectorized global reductions ------------------------------
__device__ __forceinline__ void red_add_v2f16x2(uint2* addr, uint2 v) {
    asm volatile("red.global.add.noftz.v2.f16x2 [%0], {%1,%2};"
                 :: "l"(addr), "r"(v.x), "r"(v.y) : "memory");
}
__device__ __forceinline__ void red_add_v4f16x2(uint4* addr, uint4 v) {
    asm volatile("red.global.add.noftz.v4.f16x2 [%0], {%1,%2,%3,%4};"
                 :: "l"(addr), "r"(v.x), "r"(v.y), "r"(v.z), "r"(v.w) : "memory");
}

// ---------------- K0: verts -> e4m3x4 (8x,8y,8z,8); zero agg1h -------------
__global__ void k0_pad(const float* __restrict__ verts) {
    int v = blockIdx.x * blockDim.x + threadIdx.x;
    if (v >= NV) return;
    float vx = verts[3*v+0], vy = verts[3*v+1], vz = verts[3*v+2];
    uint lo = enc8(VSCALE*vx, VSCALE*vy);
    uint hi = enc8(VSCALE*vz, VSCALE);
    g_v8[v] = lo | (hi << 16);
    g_agg1h[v] = make_uint2(0u, 0u);
}

// ---------------- K1: edge pass 1 (4B gather + 8B red); zero agg2h ---------
__global__ void k1_edge_agg1(const int* __restrict__ edges) {
    int e = blockIdx.x * blockDim.x + threadIdx.x;
    if (e < NV) g_agg2h[e] = make_uint4(0u, 0u, 0u, 0u);   // fold memset
    if (e >= NE) return;
    int2 ep = __ldg(((const int2*)edges) + e);
    uint pi = __ldg(&g_v8[ep.x]);
    uint pj = __ldg(&g_v8[ep.y]);
    uint2 vi = make_uint2(dec8(pi & 0xffffu), dec8(pi >> 16));
    uint2 vj = make_uint2(dec8(pj & 0xffffu), dec8(pj >> 16));
    red_add_v2f16x2(&g_agg1h[ep.x], vj);
    red_add_v2f16x2(&g_agg1h[ep.y], vi);
}

// ---------------- K2: vertex pass 1 — x1 = leaky(gc1); store fp8 + fp16 ----
__global__ void k2_vert1(const float* __restrict__ verts,
                         const float* __restrict__ w0a, const float* __restrict__ b0a,
                         const float* __restrict__ w1a, const float* __restrict__ b1a) {
    int v = blockIdx.x * blockDim.x + threadIdx.x;
    if (v >= NV) return;
    float p[3];
    p[0] = verts[3*v+0]; p[1] = verts[3*v+1]; p[2] = verts[3*v+2];
    uint2 ar = g_agg1h[v];
    float2 a01 = __half22float2(*reinterpret_cast<__half2*>(&ar.x));
    float2 a2d = __half22float2(*reinterpret_cast<__half2*>(&ar.y));
    float a[3] = {a01.x * VINV, a01.y * VINV, a2d.x * VINV};
    float dg = a2d.y * VINV;   // degree (exact: 8*n in fp16, n<=2048)
    float x[5];
#pragma unroll
    for (int k = 0; k < 5; k++) {
        float t = __ldg(b0a + k) + dg * __ldg(b1a + k);
#pragma unroll
        for (int c = 0; c < 3; c++)
            t += __ldg(w0a + k*3 + c) * p[c] + __ldg(w1a + k*3 + c) * a[c];
        x[k] = leaky(t);
    }
    // fp16 exact-path copy (for k4 self-term)
    __half2 p01 = __floats2half2_rn(x[0], x[1]);
    __half2 p23 = __floats2half2_rn(x[2], x[3]);
    __half2 p4z = __floats2half2_rn(x[4], 0.f);
    uint4 o;
    o.x = *(uint*)&p01; o.y = *(uint*)&p23; o.z = *(uint*)&p4z; o.w = 0u;
    g_x1h[v] = o;
    // fp8 gather copy (scaled by 32)
    uint2 o8;
    o8.x = (uint)enc8(XSCALE*x[0], XSCALE*x[1]) | ((uint)enc8(XSCALE*x[2], XSCALE*x[3]) << 16);
    o8.y = (uint)enc8(XSCALE*x[4], 0.f);
    g_x18[v] = o8;
}

// ---------------- K3: edge pass 2 — fp8 gather (8B) + fp16 red (16B) -------
__global__ void k3_edge_agg2(const int* __restrict__ edges) {
    int e = blockIdx.x * blockDim.x + threadIdx.x;
    if (e >= NE) return;
    int2 ep = __ldg(((const int2*)edges) + e);
    uint2 pj = __ldg(&g_x18[ep.y]);
    uint2 pi = __ldg(&g_x18[ep.x]);
    uint4 xj = make_uint4(dec8(pj.x & 0xffffu), dec8(pj.x >> 16), dec8(pj.y & 0xffffu), 0u);
    uint4 xi = make_uint4(dec8(pi.x & 0xffffu), dec8(pi.x >> 16), dec8(pi.y & 0xffffu), 0u);
    red_add_v4f16x2(&g_agg2h[ep.x], xj);
    red_add_v4f16x2(&g_agg2h[ep.y], xi);
}

// ---------------- K4: fused gc2 + leaky + fc1 + leaky (f32x2) --------------
__global__ void k4_vert2_fc1(const float* __restrict__ w0b, const float* __restrict__ b0b,
                             const float* __restrict__ w1b, const float* __restrict__ b1b,
                             const float* __restrict__ fc1_w, const float* __restrict__ fc1_b) {
    __shared__ float2 sAB[100];   // (w0b[k][c], w1b[k][c]) at k*5+c
    __shared__ float2 sF[100];    // (fc1_w[m][2q], fc1_w[m][2q+1]) at m*10+q
    __shared__ float  sb0[20], sb1[20], sfb[10];
    int t = threadIdx.x;
    if (t < 100) {
        sAB[t] = make_float2(w0b[t], w1b[t]);
        sF[t]  = ((const float2*)fc1_w)[t];
    }
    if (t < 20) { sb0[t] = b0b[t]; sb1[t] = b1b[t]; }
    if (t < 10) { sfb[t] = fc1_b[t]; }
    __syncthreads();

    int v = blockIdx.x * blockDim.x + threadIdx.x;
    if (v >= NV) return;
    if (v < BATCH*NOUT) g_logits[v] = 0.f;   // fold memset (k5 runs after)

    uint4 xr = g_x1h[v];
    uint4 ar = g_agg2h[v];
    float2 x01 = __half22float2(*reinterpret_cast<__half2*>(&xr.x));
    float2 x23 = __half22float2(*reinterpret_cast<__half2*>(&xr.y));
    float2 x4_ = __half22float2(*reinterpret_cast<__half2*>(&xr.z));
    float2 a01 = __half22float2(*reinterpret_cast<__half2*>(&ar.x));
    float2 a23 = __half22float2(*reinterpret_cast<__half2*>(&ar.y));
    float2 a4_ = __half22float2(*reinterpret_cast<__half2*>(&ar.z));
    float xv[5] = {x01.x, x01.y, x23.x, x23.y, x4_.x};
    float av[5] = {a01.x * XINV, a01.y * XINV, a23.x * XINV, a23.y * XINV, a4_.x * XINV};
    uint2 dr = g_agg1h[v];
    float dg = __half22float2(*reinterpret_cast<__half2*>(&dr.y)).y * VINV;

    ull xa[5];
#pragma unroll
    for (int c = 0; c < 5; c++) xa[c] = pack2(xv[c], av[c]);

    float x2[20];
#pragma unroll
    for (int k = 0; k < 20; k++) {
        ull acc = pack2(fmaf(dg, sb1[k], sb0[k]), 0.f);
#pragma unroll
        for (int c = 0; c < 5; c++)
            ffma2(acc, xa[c], *(const ull*)&sAB[k*5 + c]);
        float2 r = unpack2(acc);
        x2[k] = leaky(r.x + r.y);
    }

    ull x2p[10];
#pragma unroll
    for (int q = 0; q < 10; q++) x2p[q] = pack2(x2[2*q], x2[2*q+1]);

    uint hm[5];
#pragma unroll
    for (int m = 0; m < 10; m += 2) {
        ull acc0 = pack2(sfb[m],   0.f);
        ull acc1 = pack2(sfb[m+1], 0.f);
#pragma unroll
        for (int q = 0; q < 10; q++) {
            ffma2(acc0, x2p[q], *(const ull*)&sF[m*10 + q]);
            ffma2(acc1, x2p[q], *(const ull*)&sF[(m+1)*10 + q]);
        }
        float2 r0 = unpack2(acc0);
        float2 r1 = unpack2(acc1);
        __half2 hp = __floats2half2_rn(leaky(r0.x + r0.y), leaky(r1.x + r1.y));
        hm[m >> 1] = *(uint*)&hp;
    }
    uint* dst = (uint*)&g_hh[(size_t)v*10];
#pragma unroll
    for (int q = 0; q < 5; q++) dst[q] = hm[q];   // 4B aligned (offset 20B*v)
}

// ---------------- K5: fc2 GEMM (fp16 h, f32x2 math, reg double-buffer) -----
#define KSUB 32
#define CHUNK 608    // 19*32
#define NCHUNK 97    // 97*608 = 58976 >= 58500
#define SWP 66       // sw row pad (even -> 8B-aligned LDS.64)

__global__ void k5_fc2(const float* __restrict__ w) {
    __shared__ float sw[KSUB*SWP];   // [kk][o]  transposed weight tile
    __shared__ float sh[64*33];      // [row][kk]
    int tid = threadIdx.x;
    int oq = tid & 15;     // outputs oq*4 .. oq*4+3
    int bq = tid >> 4;     // rows    bq*4 .. bq*4+3 within btile
    int btile = blockIdx.y;
    int kbeg = blockIdx.x * CHUNK;
    int kend = kbeg + CHUNK; if (kend > KDIM) kend = KDIM;

    int lrow = tid >> 5, lcol = tid & 31;
    const float*  wbase = w + (size_t)lrow * KDIM;
    const __half* hbase = &g_hh[(size_t)(btile*64 + lrow) * KDIM];

    ull acc[4][2];
#pragma unroll
    for (int a = 0; a < 4; a++) { acc[a][0] = 0ull; acc[a][1] = 0ull; }

    float rw[8]; __half rh[8];
    {
        int k = kbeg + lcol;
        bool ok = k < kend;
#pragma unroll
        for (int it = 0; it < 8; it++) {
            rw[it] = ok ? __ldg(wbase + (size_t)(it*8) * KDIM + k) : 0.f;
            rh[it] = ok ? __ldg(hbase + (size_t)(it*8) * KDIM + k) : __half(0.f);
        }
    }

    for (int k0 = kbeg; k0 < kend; k0 += KSUB) {
#pragma unroll
        for (int it = 0; it < 8; it++) {
            int row = lrow + it*8;
            sw[lcol*SWP + row] = rw[it];
            sh[row*33 + lcol]  = __half2float(rh[it]);
        }
        __syncthreads();
        int kn = k0 + KSUB + lcol;
        if (k0 + KSUB < kend) {
            bool ok = kn < kend;
#pragma unroll
            for (int it = 0; it < 8; it++) {
                rw[it] = ok ? __ldg(wbase + (size_t)(it*8) * KDIM + kn) : 0.f;
                rh[it] = ok ? __ldg(hbase + (size_t)(it*8) * KDIM + kn) : __half(0.f);
            }
        }
#pragma unroll 4
        for (int kk = 0; kk < KSUB; kk++) {
            ull w01 = *(const ull*)&sw[kk*SWP + oq*4];
            ull w23 = *(const ull*)&sw[kk*SWP + oq*4 + 2];
#pragma unroll
            for (int a = 0; a < 4; a++) {
                float hv = sh[(bq*4 + a)*33 + kk];
                ull h2 = pack2(hv, hv);
                ffma2(acc[a][0], h2, w01);
                ffma2(acc[a][1], h2, w23);
            }
        }
        __syncthreads();
    }
#pragma unroll
    for (int a = 0; a < 4; a++) {
        float2 r0 = unpack2(acc[a][0]);
        float2 r1 = unpack2(acc[a][1]);
        float* dst = &g_logits[(btile*64 + bq*4 + a) * NOUT + oq*4];
        atomicAdd(dst + 0, r0.x);
        atomicAdd(dst + 1, r0.y);
        atomicAdd(dst + 2, r1.x);
        atomicAdd(dst + 3, r1.y);
    }
}

// ---------------- K6: bias + softmax over 64 -------------------------------
__global__ void k6_softmax(const float* __restrict__ fc2_b, float* __restrict__ out) {
    int b = blockIdx.x;
    int t = threadIdx.x;  // 64
    __shared__ float s[64];
    float x = g_logits[b*NOUT + t] + fc2_b[t];
    s[t] = x; __syncthreads();
#pragma unroll
    for (int off = 32; off > 0; off >>= 1) {
        if (t < off) s[t] = fmaxf(s[t], s[t + off]);
        __syncthreads();
    }
    float m = s[0];
    __syncthreads();
    float e = expf(x - m);
    s[t] = e; __syncthreads();
#pragma unroll
    for (int off = 32; off > 0; off >>= 1) {
        if (t < off) s[t] = s[t] + s[t + off];
        __syncthreads();
    }
    float sum = s[0];
    out[b*NOUT + t] = e / sum;
}

// ---------------- launch ----------------------------------------------------
extern "C" void kernel_launch(void* const* d_in, const int* in_sizes, int n_in,
                              void* d_out, int out_size) {
    const float* verts = (const float*)d_in[0];
    const int*   edges = (const int*)  d_in[1];   // int32
    const float* w0a = (const float*)d_in[2];
    const float* b0a = (const float*)d_in[3];
    const float* w1a = (const float*)d_in[4];
    const float* b1a = (const float*)d_in[5];
    const float* w0b = (const float*)d_in[6];
    const float* b0b = (const float*)d_in[7];
    const float* w1b = (const float*)d_in[8];
    const float* b1b = (const float*)d_in[9];
    const float* fc1_w = (const float*)d_in[10];
    const float* fc1_b = (const float*)d_in[11];
    const float* fc2_w = (const float*)d_in[12];
    const float* fc2_b = (const float*)d_in[13];
    float* out = (float*)d_out;

    const int TB = 256;
    int eblocks = (NE + TB - 1) / TB;
    int vblocks = (NV + TB - 1) / TB;

    k0_pad      <<<vblocks, TB>>>(verts);
    k1_edge_agg1<<<eblocks, TB>>>(edges);
    k2_vert1    <<<vblocks, TB>>>(verts, w0a, b0a, w1a, b1a);
    k3_edge_agg2<<<eblocks, TB>>>(edges);
    k4_vert2_fc1<<<vblocks, TB>>>(w0b, b0b, w1b, b1b, fc1_w, fc1_b);
    dim3 g5(NCHUNK, 4);
    k5_fc2      <<<g5, 256>>>(fc2_w);
    k6_softmax  <<<BATCH, 64>>>(fc2_b, out);
}

// round 7
// speedup vs baseline: 2.4365x; 1.0602x over previous
#include <cuda_runtime.h>
#include <cuda_fp16.h>
#include <cuda_bf16.h>

// Problem constants
#define BATCH 256
#define VPM   5850
#define NV    (BATCH*VPM)      // 1,497,600 vertices
#define NE    (3*NV)           // 4,492,800 edges
#define KDIM  (VPM*10)         // 58,500
#define NOUT  64
#define NEG_SLOPE 0.01f

#define VSCALE 8.0f            // fp8 scale for verts (and degree lane)
#define VINV   0.125f
#define XSCALE 32.0f           // fp8 scale for x1
#define XINV   0.03125f

typedef unsigned long long ull;
typedef unsigned int uint;
typedef unsigned short ushort;

// ---------------- scratch (device globals: allocation-free) ----------------
__device__ uint   g_v8[NV];            //  6 MB verts as e4m3x4 (8x,8y,8z,8)
__device__ uint2  g_agg1h[NV];         // 12 MB (8Sx,8Sy,8Sz,8deg) fp16
__device__ uint2  g_x18[NV];           // 12 MB x1 e4m3 x5 (32x) + deg fp16 in y-hi
__device__ uint4  g_agg2h[NV];         // 24 MB agg2 as 8 fp16 (5 used, 32x scale)
__device__ __half g_hh[(size_t)NV*10]; // 30 MB h fp16 == (B, 58500) row-major
__device__ __half g_wh[(size_t)NOUT*KDIM]; // 7.5 MB fc2_w fp16
__device__ float  g_logits[BATCH*NOUT];// 64 KB

__device__ __forceinline__ float leaky(float t) {
    return t >= 0.f ? t : NEG_SLOPE * t;
}

// ---------------- f32x2 packed-FMA helpers ----------------------------------
__device__ __forceinline__ void ffma2(ull& d, ull a, ull b) {
    asm("fma.rn.f32x2 %0, %1, %2, %0;" : "+l"(d) : "l"(a), "l"(b));
}
__device__ __forceinline__ ull pack2(float lo, float hi) {
    ull r; asm("mov.b64 %0, {%1,%2};" : "=l"(r) : "f"(lo), "f"(hi)); return r;
}
__device__ __forceinline__ float2 unpack2(ull v) {
    float2 r; asm("mov.b64 {%0,%1}, %2;" : "=f"(r.x), "=f"(r.y) : "l"(v)); return r;
}

// ---------------- fp8 encode/decode -----------------------------------------
__device__ __forceinline__ ushort enc8(float lo, float hi) {
    ushort r;
    asm("cvt.rn.satfinite.e4m3x2.f32 %0, %1, %2;" : "=h"(r) : "f"(hi), "f"(lo));
    return r;
}
__device__ __forceinline__ uint dec8(uint v) {
    uint r;
    asm("cvt.rn.f16x2.e4m3x2 %0, %1;" : "=r"(r) : "h"((ushort)v));
    return r;
}

// ---------------- vectorized global reductions ------------------------------
__device__ __forceinline__ void red_add_v2f16x2(uint2* addr, uint2 v) {
    asm volatile("red.global.add.noftz.v2.f16x2 [%0], {%1,%2};"
                 :: "l"(addr), "r"(v.x), "r"(v.y) : "memory");
}
__device__ __forceinline__ void red_add_v4f16x2(uint4* addr, uint4 v) {
    asm volatile("red.global.add.noftz.v4.f16x2 [%0], {%1,%2,%3,%4};"
                 :: "l"(addr), "r"(v.x), "r"(v.y), "r"(v.z), "r"(v.w) : "memory");
}

// ---------------- K0: verts -> e4m3x4 (8x,8y,8z,8); zero agg1h -------------
__global__ void k0_pad(const float* __restrict__ verts) {
    int v = blockIdx.x * blockDim.x + threadIdx.x;
    if (v >= NV) return;
    float vx = verts[3*v+0], vy = verts[3*v+1], vz = verts[3*v+2];
    uint lo = enc8(VSCALE*vx, VSCALE*vy);
    uint hi = enc8(VSCALE*vz, VSCALE);
    g_v8[v] = lo | (hi << 16);
    g_agg1h[v] = make_uint2(0u, 0u);
}

// ---------------- KP: fc2_w fp32 -> fp16 ------------------------------------
__global__ void kp_wconv(const float* __restrict__ w) {
    int i = blockIdx.x * blockDim.x + threadIdx.x;   // uint-pair units
    const int n = NOUT*KDIM/8;                       // 468000
    if (i >= n) return;
    float4 a = __ldg(((const float4*)w) + 2*i);
    float4 b = __ldg(((const float4*)w) + 2*i + 1);
    __half2 h0 = __floats2half2_rn(a.x, a.y);
    __half2 h1 = __floats2half2_rn(a.z, a.w);
    __half2 h2 = __floats2half2_rn(b.x, b.y);
    __half2 h3 = __floats2half2_rn(b.z, b.w);
    uint4 o;
    o.x = *(uint*)&h0; o.y = *(uint*)&h1; o.z = *(uint*)&h2; o.w = *(uint*)&h3;
    ((uint4*)g_wh)[i] = o;
}

// ---------------- K1: edge pass 1 (4B gather + 8B red); zero agg2h ---------
__global__ void k1_edge_agg1(const int* __restrict__ edges) {
    int e = blockIdx.x * blockDim.x + threadIdx.x;
    if (e < NV) g_agg2h[e] = make_uint4(0u, 0u, 0u, 0u);   // fold memset
    if (e >= NE) return;
    int2 ep = __ldg(((const int2*)edges) + e);
    uint pi = __ldg(&g_v8[ep.x]);
    uint pj = __ldg(&g_v8[ep.y]);
    uint2 vi = make_uint2(dec8(pi & 0xffffu), dec8(pi >> 16));
    uint2 vj = make_uint2(dec8(pj & 0xffffu), dec8(pj >> 16));
    red_add_v2f16x2(&g_agg1h[ep.x], vj);
    red_add_v2f16x2(&g_agg1h[ep.y], vi);
}

// ---------------- K2: vertex pass 1 — x1 = leaky(gc1); store fp8+deg -------
__global__ void k2_vert1(const float* __restrict__ verts,
                         const float* __restrict__ w0a, const float* __restrict__ b0a,
                         const float* __restrict__ w1a, const float* __restrict__ b1a) {
    int v = blockIdx.x * blockDim.x + threadIdx.x;
    if (v >= NV) return;
    float p[3];
    p[0] = verts[3*v+0]; p[1] = verts[3*v+1]; p[2] = verts[3*v+2];
    uint2 ar = g_agg1h[v];
    float2 a01 = __half22float2(*reinterpret_cast<__half2*>(&ar.x));
    float2 a2d = __half22float2(*reinterpret_cast<__half2*>(&ar.y));
    float a[3] = {a01.x * VINV, a01.y * VINV, a2d.x * VINV};
    float dg = a2d.y * VINV;   // degree (exact: 8n in fp16, n<=2048)
    float x[5];
#pragma unroll
    for (int k = 0; k < 5; k++) {
        float t = __ldg(b0a + k) + dg * __ldg(b1a + k);
#pragma unroll
        for (int c = 0; c < 3; c++)
            t += __ldg(w0a + k*3 + c) * p[c] + __ldg(w1a + k*3 + c) * a[c];
        x[k] = leaky(t);
    }
    // fp8 (scaled 32x) + degree fp16 in high half of .y
    __half dgh = __float2half_rn(dg);
    uint2 o8;
    o8.x = (uint)enc8(XSCALE*x[0], XSCALE*x[1]) | ((uint)enc8(XSCALE*x[2], XSCALE*x[3]) << 16);
    o8.y = (uint)enc8(XSCALE*x[4], 0.f) | ((uint)*(ushort*)&dgh << 16);
    g_x18[v] = o8;
}

// ---------------- K3: edge pass 2 — fp8 gather (8B) + fp16 red (16B) -------
__global__ void k3_edge_agg2(const int* __restrict__ edges) {
    int e = blockIdx.x * blockDim.x + threadIdx.x;
    if (e >= NE) return;
    int2 ep = __ldg(((const int2*)edges) + e);
    uint2 pj = __ldg(&g_x18[ep.y]);
    uint2 pi = __ldg(&g_x18[ep.x]);
    uint4 xj = make_uint4(dec8(pj.x & 0xffffu), dec8(pj.x >> 16), dec8(pj.y & 0xffffu), 0u);
    uint4 xi = make_uint4(dec8(pi.x & 0xffffu), dec8(pi.x >> 16), dec8(pi.y & 0xffffu), 0u);
    red_add_v4f16x2(&g_agg2h[ep.x], xj);
    red_add_v4f16x2(&g_agg2h[ep.y], xi);
}

// ---------------- K4: fused gc2 + leaky + fc1 + leaky (f32x2) --------------
// weights pre-scaled by XINV in smem; x/agg stay in 32x domain.
__global__ void k4_vert2_fc1(const float* __restrict__ w0b, const float* __restrict__ b0b,
                             const float* __restrict__ w1b, const float* __restrict__ b1b,
                             const float* __restrict__ fc1_w, const float* __restrict__ fc1_b) {
    __shared__ float2 sAB[100];   // (w0b*XINV, w1b*XINV) at k*5+c
    __shared__ float2 sF[100];    // (fc1_w[m][2q], fc1_w[m][2q+1]) at m*10+q
    __shared__ float  sb0[20], sb1[20], sfb[10];
    int t = threadIdx.x;
    if (t < 100) {
        sAB[t] = make_float2(w0b[t]*XINV, w1b[t]*XINV);
        sF[t]  = ((const float2*)fc1_w)[t];
    }
    if (t < 20) { sb0[t] = b0b[t]; sb1[t] = b1b[t]; }
    if (t < 10) { sfb[t] = fc1_b[t]; }
    __syncthreads();

    int v = blockIdx.x * blockDim.x + threadIdx.x;
    if (v >= NV) return;
    if (v < BATCH*NOUT) g_logits[v] = 0.f;   // fold memset (k5 runs after)

    uint2 xr = g_x18[v];
    uint4 ar = g_agg2h[v];
    // x (32x domain), fp8-decoded
    float2 x01 = __half22float2(*reinterpret_cast<__half2*>(&(uint&)(xr.x = xr.x, xr.x)));  // placeholder
    uint d0 = dec8(xr.x & 0xffffu), d1 = dec8(xr.x >> 16), d2 = dec8(xr.y & 0xffffu);
    x01 = __half22float2(*reinterpret_cast<__half2*>(&d0));
    float2 x23 = __half22float2(*reinterpret_cast<__half2*>(&d1));
    float2 x4_ = __half22float2(*reinterpret_cast<__half2*>(&d2));
    float2 a01 = __half22float2(*reinterpret_cast<__half2*>(&ar.x));
    float2 a23 = __half22float2(*reinterpret_cast<__half2*>(&ar.y));
    float2 a4_ = __half22float2(*reinterpret_cast<__half2*>(&ar.z));
    float xv[5] = {x01.x, x01.y, x23.x, x23.y, x4_.x};     // 32x domain
    float av[5] = {a01.x, a01.y, a23.x, a23.y, a4_.x};     // 32x domain
    ushort dgu = (ushort)(xr.y >> 16);
    float dg = __half2float(*(const __half*)&dgu);

    ull xa[5];
#pragma unroll
    for (int c = 0; c < 5; c++) xa[c] = pack2(xv[c], av[c]);

    float x2[20];
#pragma unroll
    for (int k = 0; k < 20; k++) {
        ull acc = pack2(fmaf(dg, sb1[k], sb0[k]), 0.f);
#pragma unroll
        for (int c = 0; c < 5; c++)
            ffma2(acc, xa[c], *(const ull*)&sAB[k*5 + c]);
        float2 r = unpack2(acc);
        x2[k] = leaky(r.x + r.y);
    }

    ull x2p[10];
#pragma unroll
    for (int q = 0; q < 10; q++) x2p[q] = pack2(x2[2*q], x2[2*q+1]);

    uint hm[5];
#pragma unroll
    for (int m = 0; m < 10; m += 2) {
        ull acc0 = pack2(sfb[m],   0.f);
        ull acc1 = pack2(sfb[m+1], 0.f);
#pragma unroll
        for (int q = 0; q < 10; q++) {
            ffma2(acc0, x2p[q], *(const ull*)&sF[m*10 + q]);
            ffma2(acc1, x2p[q], *(const ull*)&sF[(m+1)*10 + q]);
        }
        float2 r0 = unpack2(acc0);
        float2 r1 = unpack2(acc1);
        __half2 hp = __floats2half2_rn(leaky(r0.x + r0.y), leaky(r1.x + r1.y));
        hm[m >> 1] = *(uint*)&hp;
    }
    uint* dst = (uint*)&g_hh[(size_t)v*10];
#pragma unroll
    for (int q = 0; q < 5; q++) dst[q] = hm[q];
}

// ---------------- K5: fc2 GEMM (fp16 w+h, f32x2, 64o x 128b tile) ----------
#define KSUB 32
#define CHUNK 384
#define NCHUNK 153   // 153*384 = 58752 >= 58500
#define SWP 66

__global__ void k5_fc2() {
    __shared__ float sw[KSUB*SWP];   // [kk][o]  transposed weight tile
    __shared__ float sh[128*33];     // [row][kk]
    int tid = threadIdx.x;
    int oq = tid & 15;     // outputs oq*4 .. +3
    int bq = tid >> 4;     // rows    bq*8 .. +7 within btile
    int btile = blockIdx.y;          // 0..1, 128 meshes each
    int kbeg = blockIdx.x * CHUNK;
    int kend = kbeg + CHUNK; if (kend > KDIM) kend = KDIM;

    int lrow = tid >> 5, lcol = tid & 31;
    const __half* wbase = g_wh + (size_t)lrow * KDIM;
    const __half* hbase = &g_hh[(size_t)(btile*128 + lrow) * KDIM];

    ull acc[8][2];
#pragma unroll
    for (int a = 0; a < 8; a++) { acc[a][0] = 0ull; acc[a][1] = 0ull; }

    __half rw[8], rh[16];
    {
        int k = kbeg + lcol;
        bool ok = k < kend;
#pragma unroll
        for (int it = 0; it < 8; it++)
            rw[it] = ok ? __ldg(wbase + (size_t)(it*8) * KDIM + k) : __half(0.f);
#pragma unroll
        for (int it = 0; it < 16; it++)
            rh[it] = ok ? __ldg(hbase + (size_t)(it*8) * KDIM + k) : __half(0.f);
    }

    for (int k0 = kbeg; k0 < kend; k0 += KSUB) {
#pragma unroll
        for (int it = 0; it < 8; it++)
            sw[lcol*SWP + lrow + it*8] = __half2float(rw[it]);
#pragma unroll
        for (int it = 0; it < 16; it++)
            sh[(lrow + it*8)*33 + lcol] = __half2float(rh[it]);
        __syncthreads();
        int kn = k0 + KSUB + lcol;
        if (k0 + KSUB < kend) {
            bool ok = kn < kend;
#pragma unroll
            for (int it = 0; it < 8; it++)
                rw[it] = ok ? __ldg(wbase + (size_t)(it*8) * KDIM + kn) : __half(0.f);
#pragma unroll
            for (int it = 0; it < 16; it++)
                rh[it] = ok ? __ldg(hbase + (size_t)(it*8) * KDIM + kn) : __half(0.f);
        }
#pragma unroll 4
        for (int kk = 0; kk < KSUB; kk++) {
            ull w01 = *(const ull*)&sw[kk*SWP + oq*4];
            ull w23 = *(const ull*)&sw[kk*SWP + oq*4 + 2];
#pragma unroll
            for (int a = 0; a < 8; a++) {
                float hv = sh[(bq*8 + a)*33 + kk];
                ull h2 = pack2(hv, hv);
                ffma2(acc[a][0], h2, w01);
                ffma2(acc[a][1], h2, w23);
            }
        }
        __syncthreads();
    }
#pragma unroll
    for (int a = 0; a < 8; a++) {
        float2 r0 = unpack2(acc[a][0]);
        float2 r1 = unpack2(acc[a][1]);
        float* dst = &g_logits[(btile*128 + bq*8 + a) * NOUT + oq*4];
        atomicAdd(dst + 0, r0.x);
        atomicAdd(dst + 1, r0.y);
        atomicAdd(dst + 2, r1.x);
        atomicAdd(dst + 3, r1.y);
    }
}

// ---------------- K6: bias + softmax over 64 -------------------------------
__global__ void k6_softmax(const float* __restrict__ fc2_b, float* __restrict__ out) {
    int b = blockIdx.x;
    int t = threadIdx.x;  // 64
    __shared__ float s[64];
    float x = g_logits[b*NOUT + t] + fc2_b[t];
    s[t] = x; __syncthreads();
#pragma unroll
    for (int off = 32; off > 0; off >>= 1) {
        if (t < off) s[t] = fmaxf(s[t], s[t + off]);
        __syncthreads();
    }
    float m = s[0];
    __syncthreads();
    float e = expf(x - m);
    s[t] = e; __syncthreads();
#pragma unroll
    for (int off = 32; off > 0; off >>= 1) {
        if (t < off) s[t] = s[t] + s[t + off];
        __syncthreads();
    }
    float sum = s[0];
    out[b*NOUT + t] = e / sum;
}

// ---------------- launch ----------------------------------------------------
extern "C" void kernel_launch(void* const* d_in, const int* in_sizes, int n_in,
                              void* d_out, int out_size) {
    const float* verts = (const float*)d_in[0];
    const int*   edges = (const int*)  d_in[1];   // int32
    const float* w0a = (const float*)d_in[2];
    const float* b0a = (const float*)d_in[3];
    const float* w1a = (const float*)d_in[4];
    const float* b1a = (const float*)d_in[5];
    const float* w0b = (const float*)d_in[6];
    const float* b0b = (const float*)d_in[7];
    const float* w1b = (const float*)d_in[8];
    const float* b1b = (const float*)d_in[9];
    const float* fc1_w = (const float*)d_in[10];
    const float* fc1_b = (const float*)d_in[11];
    const float* fc2_w = (const float*)d_in[12];
    const float* fc2_b = (const float*)d_in[13];
    float* out = (float*)d_out;

    const int TB = 256;
    int eblocks = (NE + TB - 1) / TB;
    int vblocks = (NV + TB - 1) / TB;
    int pblocks = (NOUT*KDIM/8 + TB - 1) / TB;

    k0_pad      <<<vblocks, TB>>>(verts);
    kp_wconv    <<<pblocks, TB>>>(fc2_w);
    k1_edge_agg1<<<eblocks, TB>>>(edges);
    k2_vert1    <<<vblocks, TB>>>(verts, w0a, b0a, w1a, b1a);
    k3_edge_agg2<<<eblocks, TB>>>(edges);
    k4_vert2_fc1<<<vblocks, TB>>>(w0b, b0b, w1b, b1b, fc1_w, fc1_b);
    dim3 g5(NCHUNK, 2);
    k5_fc2      <<<g5, 256>>>();
    k6_softmax  <<<BATCH, 64>>>(fc2_b, out);
}

// round 8
// speedup vs baseline: 2.8361x; 1.1640x over previous
#include <cuda_runtime.h>
#include <cuda_fp16.h>
#include <cuda_bf16.h>

// Problem constants
#define BATCH 256
#define VPM   5850
#define NV    (BATCH*VPM)      // 1,497,600 vertices
#define NE    (3*NV)           // 4,492,800 edges
#define KDIM  (VPM*10)         // 58,500
#define NOUT  64
#define NEG_SLOPE 0.01f

#define VSCALE 8.0f            // fp8 scale for verts (and degree lane)
#define VINV   0.125f
#define XSCALE 32.0f           // fp8 scale for x1
#define XINV   0.03125f

typedef unsigned long long ull;
typedef unsigned int uint;
typedef unsigned short ushort;

// ---------------- scratch (device globals: allocation-free) ----------------
__device__ uint   g_v8[NV];            //  6 MB verts as e4m3x4 (8x,8y,8z,8)
__device__ uint2  g_agg1h[NV];         // 12 MB (8Sx,8Sy,8Sz,8deg) fp16
__device__ uint2  g_x18[NV];           // 12 MB x1 e4m3 x5 (32x) + deg fp16 in y-hi
__device__ uint4  g_agg2h[NV];         // 24 MB agg2 as 8 fp16 (5 used, 32x scale)
__device__ __half g_hh[(size_t)NV*10]; // 30 MB h fp16 == (B, 58500) row-major
__device__ uint4  g_wh4[NOUT*KDIM/8];  // 7.5 MB fc2_w fp16
__device__ float  g_logits[BATCH*NOUT];// 64 KB

__device__ __forceinline__ float leaky(float t) {
    return t >= 0.f ? t : NEG_SLOPE * t;
}

// ---------------- f32x2 packed-FMA helpers ----------------------------------
__device__ __forceinline__ void ffma2(ull& d, ull a, ull b) {
    asm("fma.rn.f32x2 %0, %1, %2, %0;" : "+l"(d) : "l"(a), "l"(b));
}
__device__ __forceinline__ ull pack2(float lo, float hi) {
    ull r; asm("mov.b64 %0, {%1,%2};" : "=l"(r) : "f"(lo), "f"(hi)); return r;
}
__device__ __forceinline__ float2 unpack2(ull v) {
    float2 r; asm("mov.b64 {%0,%1}, %2;" : "=f"(r.x), "=f"(r.y) : "l"(v)); return r;
}

// ---------------- fp8 encode/decode -----------------------------------------
__device__ __forceinline__ ushort enc8(float lo, float hi) {
    ushort r;
    asm("cvt.rn.satfinite.e4m3x2.f32 %0, %1, %2;" : "=h"(r) : "f"(hi), "f"(lo));
    return r;
}
__device__ __forceinline__ uint dec8(uint v) {
    uint r;
    asm("cvt.rn.f16x2.e4m3x2 %0, %1;" : "=r"(r) : "h"((ushort)v));
    return r;
}

// ---------------- vectorized global reductions ------------------------------
__device__ __forceinline__ void red_add_v2f16x2(uint2* addr, uint2 v) {
    asm volatile("red.global.add.noftz.v2.f16x2 [%0], {%1,%2};"
                 :: "l"(addr), "r"(v.x), "r"(v.y) : "memory");
}
__device__ __forceinline__ void red_add_v4f16x2(uint4* addr, uint4 v) {
    asm volatile("red.global.add.noftz.v4.f16x2 [%0], {%1,%2,%3,%4};"
                 :: "l"(addr), "r"(v.x), "r"(v.y), "r"(v.z), "r"(v.w) : "memory");
}
__device__ __forceinline__ void red_add_v2f32(float* addr, float2 v) {
    asm volatile("red.global.add.v2.f32 [%0], {%1,%2};"
                 :: "l"(addr), "f"(v.x), "f"(v.y) : "memory");
}

// ---------------- warp mma m16n8k16 fp16 -> fp32 -----------------------------
__device__ __forceinline__ void mma16816(float* c, uint a0, uint a1, uint a2, uint a3,
                                         uint b0, uint b1) {
    asm volatile(
        "mma.sync.aligned.m16n8k16.row.col.f32.f16.f16.f32 "
        "{%0,%1,%2,%3}, {%4,%5,%6,%7}, {%8,%9}, {%0,%1,%2,%3};"
        : "+f"(c[0]), "+f"(c[1]), "+f"(c[2]), "+f"(c[3])
        : "r"(a0), "r"(a1), "r"(a2), "r"(a3), "r"(b0), "r"(b1));
}

// ---------------- K0: verts -> e4m3x4; zero agg1h; fc2_w -> fp16 ------------
__global__ void k0_pad(const float* __restrict__ verts, const float* __restrict__ w) {
    int v = blockIdx.x * blockDim.x + threadIdx.x;
    if (v >= NV) return;
    float vx = verts[3*v+0], vy = verts[3*v+1], vz = verts[3*v+2];
    uint lo = enc8(VSCALE*vx, VSCALE*vy);
    uint hi = enc8(VSCALE*vz, VSCALE);
    g_v8[v] = lo | (hi << 16);
    g_agg1h[v] = make_uint2(0u, 0u);
    if (v < NOUT*KDIM/8) {   // fold fc2_w fp32->fp16 conversion
        float4 a = __ldg(((const float4*)w) + 2*v);
        float4 b = __ldg(((const float4*)w) + 2*v + 1);
        __half2 h0 = __floats2half2_rn(a.x, a.y);
        __half2 h1 = __floats2half2_rn(a.z, a.w);
        __half2 h2 = __floats2half2_rn(b.x, b.y);
        __half2 h3 = __floats2half2_rn(b.z, b.w);
        uint4 o;
        o.x = *(uint*)&h0; o.y = *(uint*)&h1; o.z = *(uint*)&h2; o.w = *(uint*)&h3;
        g_wh4[v] = o;
    }
}

// ---------------- K1: edge pass 1 (4B gather + 8B red); zero agg2h ---------
__global__ void k1_edge_agg1(const int* __restrict__ edges) {
    int e = blockIdx.x * blockDim.x + threadIdx.x;
    if (e < NV) g_agg2h[e] = make_uint4(0u, 0u, 0u, 0u);   // fold memset
    if (e >= NE) return;
    int2 ep = __ldg(((const int2*)edges) + e);
    uint pi = __ldg(&g_v8[ep.x]);
    uint pj = __ldg(&g_v8[ep.y]);
    uint2 vi = make_uint2(dec8(pi & 0xffffu), dec8(pi >> 16));
    uint2 vj = make_uint2(dec8(pj & 0xffffu), dec8(pj >> 16));
    red_add_v2f16x2(&g_agg1h[ep.x], vj);
    red_add_v2f16x2(&g_agg1h[ep.y], vi);
}

// ---------------- K2: vertex pass 1 — x1 = leaky(gc1); store fp8+deg -------
__global__ void k2_vert1(const float* __restrict__ verts,
                         const float* __restrict__ w0a, const float* __restrict__ b0a,
                         const float* __restrict__ w1a, const float* __restrict__ b1a) {
    int v = blockIdx.x * blockDim.x + threadIdx.x;
    if (v >= NV) return;
    float p[3];
    p[0] = verts[3*v+0]; p[1] = verts[3*v+1]; p[2] = verts[3*v+2];
    uint2 ar = g_agg1h[v];
    float2 a01 = __half22float2(*reinterpret_cast<__half2*>(&ar.x));
    float2 a2d = __half22float2(*reinterpret_cast<__half2*>(&ar.y));
    float a[3] = {a01.x * VINV, a01.y * VINV, a2d.x * VINV};
    float dg = a2d.y * VINV;   // degree (exact: 8n in fp16, n<=2048)
    float x[5];
#pragma unroll
    for (int k = 0; k < 5; k++) {
        float t = __ldg(b0a + k) + dg * __ldg(b1a + k);
#pragma unroll
        for (int c = 0; c < 3; c++)
            t += __ldg(w0a + k*3 + c) * p[c] + __ldg(w1a + k*3 + c) * a[c];
        x[k] = leaky(t);
    }
    __half dgh = __float2half_rn(dg);
    uint2 o8;
    o8.x = (uint)enc8(XSCALE*x[0], XSCALE*x[1]) | ((uint)enc8(XSCALE*x[2], XSCALE*x[3]) << 16);
    o8.y = (uint)enc8(XSCALE*x[4], 0.f) | ((uint)*(ushort*)&dgh << 16);
    g_x18[v] = o8;
}

// ---------------- K3: edge pass 2 — fp8 gather (8B) + fp16 red (16B) -------
__global__ void k3_edge_agg2(const int* __restrict__ edges) {
    int e = blockIdx.x * blockDim.x + threadIdx.x;
    if (e >= NE) return;
    int2 ep = __ldg(((const int2*)edges) + e);
    uint2 pj = __ldg(&g_x18[ep.y]);
    uint2 pi = __ldg(&g_x18[ep.x]);
    uint4 xj = make_uint4(dec8(pj.x & 0xffffu), dec8(pj.x >> 16), dec8(pj.y & 0xffffu), 0u);
    uint4 xi = make_uint4(dec8(pi.x & 0xffffu), dec8(pi.x >> 16), dec8(pi.y & 0xffffu), 0u);
    red_add_v4f16x2(&g_agg2h[ep.x], xj);
    red_add_v4f16x2(&g_agg2h[ep.y], xi);
}

// ---------------- K4: fused gc2 + leaky + fc1 + leaky (f32x2) --------------
__global__ void k4_vert2_fc1(const float* __restrict__ w0b, const float* __restrict__ b0b,
                             const float* __restrict__ w1b, const float* __restrict__ b1b,
                             const float* __restrict__ fc1_w, const float* __restrict__ fc1_b) {
    __shared__ float2 sAB[100];   // (w0b*XINV, w1b*XINV) at k*5+c
    __shared__ float2 sF[100];    // (fc1_w[m][2q], fc1_w[m][2q+1]) at m*10+q
    __shared__ float  sb0[20], sb1[20], sfb[10];
    int t = threadIdx.x;
    if (t < 100) {
        sAB[t] = make_float2(w0b[t]*XINV, w1b[t]*XINV);
        sF[t]  = ((const float2*)fc1_w)[t];
    }
    if (t < 20) { sb0[t] = b0b[t]; sb1[t] = b1b[t]; }
    if (t < 10) { sfb[t] = fc1_b[t]; }
    __syncthreads();

    int v = blockIdx.x * blockDim.x + threadIdx.x;
    if (v >= NV) return;
    if (v < BATCH*NOUT) g_logits[v] = 0.f;   // fold memset (k5 runs after)

    uint2 xr = g_x18[v];
    uint4 ar = g_agg2h[v];
    uint d0 = dec8(xr.x & 0xffffu), d1 = dec8(xr.x >> 16), d2 = dec8(xr.y & 0xffffu);
    float2 x01 = __half22float2(*reinterpret_cast<__half2*>(&d0));
    float2 x23 = __half22float2(*reinterpret_cast<__half2*>(&d1));
    float2 x4_ = __half22float2(*reinterpret_cast<__half2*>(&d2));
    float2 a01 = __half22float2(*reinterpret_cast<__half2*>(&ar.x));
    float2 a23 = __half22float2(*reinterpret_cast<__half2*>(&ar.y));
    float2 a4_ = __half22float2(*reinterpret_cast<__half2*>(&ar.z));
    float xv[5] = {x01.x, x01.y, x23.x, x23.y, x4_.x};     // 32x domain
    float av[5] = {a01.x, a01.y, a23.x, a23.y, a4_.x};     // 32x domain
    ushort dgu = (ushort)(xr.y >> 16);
    float dg = __half2float(*(const __half*)&dgu);

    ull xa[5];
#pragma unroll
    for (int c = 0; c < 5; c++) xa[c] = pack2(xv[c], av[c]);

    float x2[20];
#pragma unroll
    for (int k = 0; k < 20; k++) {
        ull acc = pack2(fmaf(dg, sb1[k], sb0[k]), 0.f);
#pragma unroll
        for (int c = 0; c < 5; c++)
            ffma2(acc, xa[c], *(const ull*)&sAB[k*5 + c]);
        float2 r = unpack2(acc);
        x2[k] = leaky(r.x + r.y);
    }

    ull x2p[10];
#pragma unroll
    for (int q = 0; q < 10; q++) x2p[q] = pack2(x2[2*q], x2[2*q+1]);

    uint hm[5];
#pragma unroll
    for (int m = 0; m < 10; m += 2) {
        ull acc0 = pack2(sfb[m],   0.f);
        ull acc1 = pack2(sfb[m+1], 0.f);
#pragma unroll
        for (int q = 0; q < 10; q++) {
            ffma2(acc0, x2p[q], *(const ull*)&sF[m*10 + q]);
            ffma2(acc1, x2p[q], *(const ull*)&sF[(m+1)*10 + q]);
        }
        float2 r0 = unpack2(acc0);
        float2 r1 = unpack2(acc1);
        __half2 hp = __floats2half2_rn(leaky(r0.x + r0.y), leaky(r1.x + r1.y));
        hm[m >> 1] = *(uint*)&hp;
    }
    uint* dst = (uint*)&g_hh[(size_t)v*10];
#pragma unroll
    for (int q = 0; q < 5; q++) dst[q] = hm[q];
}

// ---------------- K5: fc2 GEMM on tensor cores (m16n8k16) ------------------
// grid (61, 2): blockIdx.x = K chunk (960), blockIdx.y = 128-row M half.
// Block 256 thr / 8 warps; warp w -> rows [w*16, w*16+16), all 64 cols.
#define K5_CHUNK  960
#define K5_GRIDX  61    // 61*960 = 58560 >= 58500
#define K5_KT     32    // halves per stage
#define SROW      40    // smem row stride in halves (conflict-free, 16B-aligned)

__global__ void k5_fc2() {
    __shared__ __align__(16) __half sA[128*SROW];
    __shared__ __align__(16) __half sB[64*SROW];
    int tid = threadIdx.x;
    int warp = tid >> 5, lane = tid & 31;
    int g = lane >> 2, t4 = lane & 3;
    int mbase = blockIdx.y * 128;
    int kbeg = blockIdx.x * K5_CHUNK;
    int klen = KDIM - kbeg; if (klen > K5_CHUNK) klen = K5_CHUNK;
    int nstages = (klen + K5_KT - 1) / K5_KT;

    const __half* hbase = g_hh;
    const __half* wbase = (const __half*)g_wh4;

    float c[8][4];
#pragma unroll
    for (int nt = 0; nt < 8; nt++)
#pragma unroll
        for (int i = 0; i < 4; i++) c[nt][i] = 0.f;

    // gmem load of one stage into regs (uint2 = 4 halves, 8B-aligned: KDIM%4==0)
    uint2 rA[4], rB[2];
    auto load_stage = [&](int s) {
        int k0 = kbeg + s * K5_KT;
#pragma unroll
        for (int i = 0; i < 4; i++) {
            int idx = tid + i * 256;           // 0..1023
            int row = idx >> 3, c2 = idx & 7;  // col = c2*4 halves
            int k = k0 + c2 * 4;
            rA[i] = (k < KDIM)
                ? __ldg((const uint2*)(hbase + (size_t)(mbase + row) * KDIM + k))
                : make_uint2(0u, 0u);
        }
#pragma unroll
        for (int i = 0; i < 2; i++) {
            int idx = tid + i * 256;           // 0..511
            int row = idx >> 3, c2 = idx & 7;
            int k = k0 + c2 * 4;
            rB[i] = (k < KDIM)
                ? __ldg((const uint2*)(wbase + (size_t)row * KDIM + k))
                : make_uint2(0u, 0u);
        }
    };

    load_stage(0);
    for (int s = 0; s < nstages; s++) {
        // regs -> smem
#pragma unroll
        for (int i = 0; i < 4; i++) {
            int idx = tid + i * 256;
            int row = idx >> 3, c2 = idx & 7;
            *(uint2*)&sA[row * SROW + c2 * 4] = rA[i];
        }
#pragma unroll
        for (int i = 0; i < 2; i++) {
            int idx = tid + i * 256;
            int row = idx >> 3, c2 = idx & 7;
            *(uint2*)&sB[row * SROW + c2 * 4] = rB[i];
        }
        __syncthreads();
        if (s + 1 < nstages) load_stage(s + 1);

        int wm = warp * 16;
#pragma unroll
        for (int kk = 0; kk < 2; kk++) {
            int kc = kk * 16;
            uint a0 = *(const uint*)&sA[(wm + g    ) * SROW + kc     + 2*t4];
            uint a1 = *(const uint*)&sA[(wm + g + 8) * SROW + kc     + 2*t4];
            uint a2 = *(const uint*)&sA[(wm + g    ) * SROW + kc + 8 + 2*t4];
            uint a3 = *(const uint*)&sA[(wm + g + 8) * SROW + kc + 8 + 2*t4];
#pragma unroll
            for (int nt = 0; nt < 8; nt++) {
                uint b0 = *(const uint*)&sB[(nt*8 + g) * SROW + kc     + 2*t4];
                uint b1 = *(const uint*)&sB[(nt*8 + g) * SROW + kc + 8 + 2*t4];
                mma16816(c[nt], a0, a1, a2, a3, b0, b1);
            }
        }
        __syncthreads();
    }

    // epilogue: vectorized float2 reductions into logits
    int row0 = mbase + warp * 16 + g;
#pragma unroll
    for (int nt = 0; nt < 8; nt++) {
        int col = nt * 8 + 2 * t4;
        red_add_v2f32(&g_logits[row0 * NOUT + col],       make_float2(c[nt][0], c[nt][1]));
        red_add_v2f32(&g_logits[(row0 + 8) * NOUT + col], make_float2(c[nt][2], c[nt][3]));
    }
}

// ---------------- K6: bias + softmax over 64 -------------------------------
__global__ void k6_softmax(const float* __restrict__ fc2_b, float* __restrict__ out) {
    int b = blockIdx.x;
    int t = threadIdx.x;  // 64
    __shared__ float s[64];
    float x = g_logits[b*NOUT + t] + fc2_b[t];
    s[t] = x; __syncthreads();
#pragma unroll
    for (int off = 32; off > 0; off >>= 1) {
        if (t < off) s[t] = fmaxf(s[t], s[t + off]);
        __syncthreads();
    }
    float m = s[0];
    __syncthreads();
    float e = expf(x - m);
    s[t] = e; __syncthreads();
#pragma unroll
    for (int off = 32; off > 0; off >>= 1) {
        if (t < off) s[t] = s[t] + s[t + off];
        __syncthreads();
    }
    float sum = s[0];
    out[b*NOUT + t] = e / sum;
}

// ---------------- launch ----------------------------------------------------
extern "C" void kernel_launch(void* const* d_in, const int* in_sizes, int n_in,
                              void* d_out, int out_size) {
    const float* verts = (const float*)d_in[0];
    const int*   edges = (const int*)  d_in[1];   // int32
    const float* w0a = (const float*)d_in[2];
    const float* b0a = (const float*)d_in[3];
    const float* w1a = (const float*)d_in[4];
    const float* b1a = (const float*)d_in[5];
    const float* w0b = (const float*)d_in[6];
    const float* b0b = (const float*)d_in[7];
    const float* w1b = (const float*)d_in[8];
    const float* b1b = (const float*)d_in[9];
    const float* fc1_w = (const float*)d_in[10];
    const float* fc1_b = (const float*)d_in[11];
    const float* fc2_w = (const float*)d_in[12];
    const float* fc2_b = (const float*)d_in[13];
    float* out = (float*)d_out;

    const int TB = 256;
    int eblocks = (NE + TB - 1) / TB;
    int vblocks = (NV + TB - 1) / TB;

    k0_pad      <<<vblocks, TB>>>(verts, fc2_w);
    k1_edge_agg1<<<eblocks, TB>>>(edges);
    k2_vert1    <<<vblocks, TB>>>(verts, w0a, b0a, w1a, b1a);
    k3_edge_agg2<<<eblocks, TB>>>(edges);
    k4_vert2_fc1<<<vblocks, TB>>>(w0b, b0b, w1b, b1b, fc1_w, fc1_b);
    dim3 g5(K5_GRIDX, 2);
    k5_fc2      <<<g5, 256>>>();
    k6_softmax  <<<BATCH, 64>>>(fc2_b, out);
}